// round 1
// baseline (speedup 1.0000x reference)
#include <cuda_runtime.h>
#include <math.h>

#define NEG        (-1.0e9f)
#define SCORE_TH   (0.05f)
#define IOU_TH     (0.5f)
#define MAXDET     100

#define BLOCK      512
#define ITEMS      20     // supports N  <= 512*20 = 10240
#define ITEMS2     16     // supports C*M <= 512*16 = 8192
#define PAD_NEG    (-3.402823466e+38f)   // below NEG sentinel

// Scratch: per-(b,c,m) kept score + box. Sized for B<=4, C<=128.
__device__ float  g_sc[4 * 128 * MAXDET];
__device__ float4 g_bx[4 * 128 * MAXDET];

// ---- packed argmax key: (orderable score bits << 32) | ~idx ----
// max(key) => max score, ties broken toward LOWEST index (matches jnp.argmax / top_k).
__device__ __forceinline__ unsigned long long packKey(float s, unsigned idx) {
    unsigned u = __float_as_uint(s);
    u = (u & 0x80000000u) ? ~u : (u | 0x80000000u);
    return ((unsigned long long)u << 32) | (unsigned)(~idx);
}
__device__ __forceinline__ float keyScore(unsigned long long k) {
    unsigned u = (unsigned)(k >> 32);
    u = (u & 0x80000000u) ? (u & 0x7FFFFFFFu) : ~u;
    return __uint_as_float(u);
}
__device__ __forceinline__ unsigned keyIdx(unsigned long long k) {
    return ~(unsigned)(k & 0xFFFFFFFFu);
}

// Block-wide max of packed keys across BLOCK threads. red[] must hold BLOCK/32 u64.
__device__ __forceinline__ unsigned long long blockKeyMax(unsigned long long k,
                                                          unsigned long long* red) {
    int lane = threadIdx.x & 31;
    int wid  = threadIdx.x >> 5;
    #pragma unroll
    for (int o = 16; o > 0; o >>= 1) {
        unsigned long long other = __shfl_down_sync(0xFFFFFFFFu, k, o);
        if (other > k) k = other;
    }
    if (lane == 0) red[wid] = k;
    __syncthreads();
    if (wid == 0) {
        unsigned long long v = (lane < (BLOCK / 32)) ? red[lane] : 0ULL;
        #pragma unroll
        for (int o = 8; o > 0; o >>= 1) {
            unsigned long long other = __shfl_down_sync(0xFFFFFFFFu, v, o);
            if (other > v) v = other;
        }
        if (lane == 0) red[0] = v;
    }
    __syncthreads();
    unsigned long long r = red[0];
    __syncthreads();   // red[] is reused next call
    return r;
}

// ======================== Kernel 1: per-(b,c) greedy NMS ========================
__global__ void __launch_bounds__(BLOCK, 1)
nms_kernel(const float4* __restrict__ boxes, const float* __restrict__ cls,
           int N, int C) {
    const int c = blockIdx.x;
    const int b = blockIdx.y;
    const int t = threadIdx.x;

    __shared__ unsigned long long red[BLOCK / 32];
    __shared__ float4 sbox;

    float  s[ITEMS];
    float4 bx[ITEMS];

    const float4* bp = boxes + (size_t)b * N;
    #pragma unroll
    for (int j = 0; j < ITEMS; j++) {
        int i = j * BLOCK + t;
        if (i < N) {
            bx[j] = bp[i];
            float sc = cls[((size_t)b * N + i) * C + c];
            s[j] = (sc > SCORE_TH) ? sc : NEG;
        } else {
            bx[j] = make_float4(0.f, 0.f, 0.f, 0.f);
            s[j]  = PAD_NEG;
        }
    }

    const int base = (b * C + c) * MAXDET;

    for (int m = 0; m < MAXDET; m++) {
        unsigned long long k = 0ULL;
        #pragma unroll
        for (int j = 0; j < ITEMS; j++) {
            unsigned long long kk = packKey(s[j], (unsigned)(j * BLOCK + t));
            if (kk > k) k = kk;
        }
        k = blockKeyMax(k, red);
        float    bscore = keyScore(k);
        unsigned bidx   = keyIdx(k);

        if (!(bscore > SCORE_TH)) {
            // Everything left is the NEG sentinel: remaining kept rows are all
            // invalid in the final output. Fill and stop (output-equivalent to
            // the reference's remaining scan steps).
            for (int mm = m + t; mm < MAXDET; mm += BLOCK) {
                g_sc[base + mm] = NEG;
                g_bx[base + mm] = make_float4(0.f, 0.f, 0.f, 0.f);
            }
            return;
        }

        int oj = bidx / BLOCK;
        int ot = bidx % BLOCK;
        if (t == ot) {
            sbox = bx[oj];
            g_sc[base + m] = bscore;
            g_bx[base + m] = bx[oj];
        }
        __syncthreads();
        float4 B0 = sbox;
        float a1 = (B0.z - B0.x) * (B0.w - B0.y);

        #pragma unroll
        for (int j = 0; j < ITEMS; j++) {
            float ix1 = fmaxf(B0.x, bx[j].x);
            float iy1 = fmaxf(B0.y, bx[j].y);
            float ix2 = fminf(B0.z, bx[j].z);
            float iy2 = fminf(B0.w, bx[j].w);
            float inter = fmaxf(ix2 - ix1, 0.0f) * fmaxf(iy2 - iy1, 0.0f);
            float a2  = (bx[j].z - bx[j].x) * (bx[j].w - bx[j].y);
            float uni = fmaxf(a1 + a2 - inter, 1e-8f);
            float iou = __fdiv_rn(inter, uni);   // IEEE divide: match XLA at the >0.5 boundary
            if (iou > IOU_TH) s[j] = NEG;
        }
        // no extra sync needed: blockKeyMax's internal barriers order sbox reuse
    }
}

// ==================== Kernel 2: per-image top-100 over C*M ====================
__global__ void __launch_bounds__(BLOCK, 1)
topk_kernel(float* __restrict__ out, int B, int C) {
    const int b  = blockIdx.x;
    const int t  = threadIdx.x;
    const int CM = C * MAXDET;

    __shared__ unsigned long long red[BLOCK / 32];

    float s[ITEMS2];
    const int base = b * CM;
    #pragma unroll
    for (int j = 0; j < ITEMS2; j++) {
        int i = j * BLOCK + t;
        s[j] = (i < CM) ? g_sc[base + i] : PAD_NEG;
    }

    float* oBoxes  = out;                               // (B, M, 4)
    float* oScores = out + (size_t)B * MAXDET * 4;      // (B, M)
    float* oLabels = out + (size_t)B * MAXDET * 5;      // (B, M) as float

    for (int r = 0; r < MAXDET; r++) {
        unsigned long long k = 0ULL;
        #pragma unroll
        for (int j = 0; j < ITEMS2; j++) {
            unsigned long long kk = packKey(s[j], (unsigned)(j * BLOCK + t));
            if (kk > k) k = kk;
        }
        k = blockKeyMax(k, red);
        float    sc  = keyScore(k);
        unsigned idx = keyIdx(k);

        int oj = idx / BLOCK;
        int ot = idx % BLOCK;
        if (t == ot) {
            s[oj] = PAD_NEG;                 // remove from candidate set
            bool valid = (sc > SCORE_TH);
            float4 bb = g_bx[base + idx];
            float* ob = oBoxes + ((size_t)b * MAXDET + r) * 4;
            ob[0] = valid ? bb.x : -1.0f;
            ob[1] = valid ? bb.y : -1.0f;
            ob[2] = valid ? bb.z : -1.0f;
            ob[3] = valid ? bb.w : -1.0f;
            oScores[b * MAXDET + r] = valid ? sc : -1.0f;
            oLabels[b * MAXDET + r] = valid ? (float)(idx / MAXDET) : -1.0f;
        }
        // blockKeyMax's barriers separate iterations
    }
}

extern "C" void kernel_launch(void* const* d_in, const int* in_sizes, int n_in,
                              void* d_out, int out_size) {
    const float4* boxes = (const float4*)d_in[0];   // (B, N, 4) f32
    const float*  cls   = (const float*)d_in[1];    // (B, N, C) f32
    float*        out   = (float*)d_out;            // boxes | scores | labels, f32

    // Derive shapes: out_size = B * (4*M + M + M) = B * 6 * M
    int B = out_size / (6 * MAXDET);
    if (B < 1) B = 1;
    int N = in_sizes[0] / (4 * B);
    int C = in_sizes[1] / (B * N);

    if (N > BLOCK * ITEMS || C * MAXDET > BLOCK * ITEMS2 || B * C > 4 * 128) {
        return;  // outside compiled capacity (fixed problem shapes fit: B=2,N=10000,C=80)
    }

    dim3 grid1(C, B);
    nms_kernel<<<grid1, BLOCK>>>(boxes, cls, N, C);
    topk_kernel<<<B, BLOCK>>>(out, B, C);
}

// round 2
// speedup vs baseline: 2.7084x; 2.7084x over previous
#include <cuda_runtime.h>
#include <math.h>

#define NEG        (-1.0e9f)
#define SCORE_TH   (0.05f)
#define MAXDET     100

#define BLOCK      512
#define ITEMS      20                 // N    <= 512*20 = 10240
#define ITEMS2     16                 // C*M  <= 512*16 = 8192
#define NPAD       (BLOCK * ITEMS)
#define PAD_NEG    (-3.402823466e+38f)

// Scratch: per-(b,c,m) kept score + box. Sized for B<=4, C<=128.
__device__ float  g_sc[4 * 128 * MAXDET];
__device__ float4 g_bx[4 * 128 * MAXDET];

// ---- packed argmax key: (orderable score bits << 32) | ~idx ----
// max(key) => max score, ties broken toward LOWEST index (matches jnp.argmax / top_k).
__device__ __forceinline__ unsigned long long packKey(float s, unsigned idx) {
    unsigned u = __float_as_uint(s);
    u = (u & 0x80000000u) ? ~u : (u | 0x80000000u);
    return ((unsigned long long)u << 32) | (unsigned)(~idx);
}
__device__ __forceinline__ float keyScore(unsigned long long k) {
    unsigned u = (unsigned)(k >> 32);
    u = (u & 0x80000000u) ? (u & 0x7FFFFFFFu) : ~u;
    return __uint_as_float(u);
}
__device__ __forceinline__ unsigned keyIdx(unsigned long long k) {
    return ~(unsigned)(k & 0xFFFFFFFFu);
}

// Block-wide max of packed keys (512 threads = 16 warps). buf = u64[17],
// caller double-buffers so only 2 barriers per call are needed.
__device__ __forceinline__ unsigned long long blockKeyMax(unsigned long long k,
                                                          unsigned long long* buf) {
    int lane = threadIdx.x & 31;
    int wid  = threadIdx.x >> 5;
    #pragma unroll
    for (int o = 16; o > 0; o >>= 1) {
        unsigned long long other = __shfl_down_sync(0xFFFFFFFFu, k, o);
        if (other > k) k = other;
    }
    if (lane == 0) buf[wid] = k;
    __syncthreads();
    if (wid == 0) {
        unsigned long long v = buf[lane & 15];
        #pragma unroll
        for (int o = 8; o > 0; o >>= 1) {
            unsigned long long other = __shfl_down_sync(0xFFFFFFFFu, v, o);
            if (other > v) v = other;
        }
        if (lane == 0) buf[16] = v;
    }
    __syncthreads();
    return buf[16];
}

// ======================== Kernel 1: per-(b,c) greedy NMS ========================
__global__ void __launch_bounds__(BLOCK, 1)
nms_kernel(const float4* __restrict__ boxes, const float* __restrict__ cls,
           int N, int C) {
    extern __shared__ float4 sbx[];                  // NPAD boxes, 160 KB
    __shared__ unsigned long long red[2][17];

    const int c = blockIdx.x;
    const int b = blockIdx.y;
    const int t = threadIdx.x;

    float s[ITEMS];
    float a2[ITEMS];

    const float4* bp = boxes + (size_t)b * N;
    const float*  cp = cls + ((size_t)b * N) * C + c;
    #pragma unroll
    for (int j = 0; j < ITEMS; j++) {
        int i = j * BLOCK + t;
        if (i < N) {
            float4 b4 = bp[i];
            sbx[i] = b4;
            a2[j]  = (b4.z - b4.x) * (b4.w - b4.y);
            float sc = cp[(size_t)i * C];
            s[j] = (sc > SCORE_TH) ? sc : NEG;
        } else {
            sbx[i] = make_float4(0.f, 0.f, 0.f, 0.f);
            a2[j]  = 0.f;
            s[j]   = PAD_NEG;
        }
    }
    __syncthreads();

    const int base = (b * C + c) * MAXDET;

    for (int m = 0; m < MAXDET; m++) {
        // local argmax, strict > keeps lowest local j => lowest global idx for this t
        float bm = s[0]; int bj = 0;
        #pragma unroll
        for (int j = 1; j < ITEMS; j++)
            if (s[j] > bm) { bm = s[j]; bj = j; }

        unsigned long long k = packKey(bm, (unsigned)(bj * BLOCK + t));
        k = blockKeyMax(k, red[m & 1]);
        float bscore = keyScore(k);

        if (!(bscore > SCORE_TH)) {
            // all remaining are the NEG sentinel -> output-invalid rows
            for (int mm = m + t; mm < MAXDET; mm += BLOCK) {
                g_sc[base + mm] = NEG;
                g_bx[base + mm] = make_float4(0.f, 0.f, 0.f, 0.f);
            }
            return;
        }

        unsigned bidx = keyIdx(k);
        float4 B0 = sbx[bidx];                       // broadcast LDS (same addr)
        if (t == 0) { g_sc[base + m] = bscore; g_bx[base + m] = B0; }
        float a1 = (B0.z - B0.x) * (B0.w - B0.y);

        #pragma unroll
        for (int j = 0; j < ITEMS; j++) {
            float4 bb = sbx[j * BLOCK + t];
            float ix1 = fmaxf(B0.x, bb.x);
            float iy1 = fmaxf(B0.y, bb.y);
            float ix2 = fminf(B0.z, bb.z);
            float iy2 = fminf(B0.w, bb.w);
            float dx = fmaxf(ix2 - ix1, 0.0f);
            float dy = fmaxf(iy2 - iy1, 0.0f);
            float inter = dx * dy;
            float u = fmaxf(a1 + a2[j] - inter, 1e-8f);
            // exact equivalent of RN(inter/u) > 0.5:
            //   inter/u > 0.5 + 2^-25  <=>  (inter - 0.5u) > 2^-25 * u
            // lhs exact via Sterbenz + single-rounding FMA wherever the
            // predicate is in doubt; rhs exact (power-of-two scale).
            float sd = fmaf(-0.5f, u, inter);
            if (sd > 2.9802322387695312e-08f * u) s[j] = NEG;
        }
        // blockKeyMax's barriers separate iterations (sbx is read-only here)
    }
}

// ==================== Kernel 2: per-image top-100 over C*M ====================
__global__ void __launch_bounds__(BLOCK, 1)
topk_kernel(float* __restrict__ out, int B, int C) {
    __shared__ unsigned long long red[2][17];
    const int b  = blockIdx.x;
    const int t  = threadIdx.x;
    const int CM = C * MAXDET;
    const int base = b * CM;

    // precompute orderable keys once; keys are unique (idx embedded)
    unsigned long long key[ITEMS2];
    #pragma unroll
    for (int j = 0; j < ITEMS2; j++) {
        int i = j * BLOCK + t;
        key[j] = (i < CM) ? packKey(g_sc[base + i], (unsigned)i) : 0ULL;
    }

    float* oBoxes  = out;                               // (B, M, 4)
    float* oScores = out + (size_t)B * MAXDET * 4;      // (B, M)
    float* oLabels = out + (size_t)B * MAXDET * 5;      // (B, M) as float

    for (int r = 0; r < MAXDET; r++) {
        // 4 independent accumulator chains to break the dependent-latency chain
        unsigned long long k0 = key[0], k1 = key[1], k2 = key[2], k3 = key[3];
        #pragma unroll
        for (int j = 4; j < ITEMS2; j += 4) {
            if (key[j]     > k0) k0 = key[j];
            if (key[j + 1] > k1) k1 = key[j + 1];
            if (key[j + 2] > k2) k2 = key[j + 2];
            if (key[j + 3] > k3) k3 = key[j + 3];
        }
        if (k1 > k0) k0 = k1;
        if (k3 > k2) k2 = k3;
        if (k2 > k0) k0 = k2;

        unsigned long long k = blockKeyMax(k0, red[r & 1]);

        // remove winner by key equality (keys unique; no dynamic reg indexing)
        #pragma unroll
        for (int j = 0; j < ITEMS2; j++)
            if (key[j] == k) key[j] = 0ULL;

        if (t == 0) {
            float    sc  = keyScore(k);
            unsigned idx = keyIdx(k);
            float bx = -1.f, by = -1.f, bz = -1.f, bw = -1.f, so = -1.f, lab = -1.f;
            if (sc > SCORE_TH) {
                float4 bb = g_bx[base + idx];
                bx = bb.x; by = bb.y; bz = bb.z; bw = bb.w;
                so = sc; lab = (float)(idx / MAXDET);
            }
            float* ob = oBoxes + ((size_t)b * MAXDET + r) * 4;
            ob[0] = bx; ob[1] = by; ob[2] = bz; ob[3] = bw;
            oScores[b * MAXDET + r] = so;
            oLabels[b * MAXDET + r] = lab;
        }
    }
}

extern "C" void kernel_launch(void* const* d_in, const int* in_sizes, int n_in,
                              void* d_out, int out_size) {
    const float4* boxes = (const float4*)d_in[0];   // (B, N, 4) f32
    const float*  cls   = (const float*)d_in[1];    // (B, N, C) f32
    float*        out   = (float*)d_out;            // boxes | scores | labels, f32

    int B = out_size / (6 * MAXDET);
    if (B < 1) B = 1;
    int N = in_sizes[0] / (4 * B);
    int C = in_sizes[1] / (B * N);

    if (N > NPAD || C * MAXDET > BLOCK * ITEMS2 || B * C > 4 * 128) {
        return;  // outside compiled capacity (fixed problem shapes fit: B=2,N=10000,C=80)
    }

    cudaFuncSetAttribute(nms_kernel, cudaFuncAttributeMaxDynamicSharedMemorySize,
                         NPAD * (int)sizeof(float4));

    dim3 grid1(C, B);
    nms_kernel<<<grid1, BLOCK, NPAD * sizeof(float4)>>>(boxes, cls, N, C);
    topk_kernel<<<B, BLOCK>>>(out, B, C);
}

// round 3
// speedup vs baseline: 12.5752x; 4.6430x over previous
#include <cuda_runtime.h>
#include <math.h>

#define NEG        (-1.0e9f)
#define SCORE_TH   (0.05f)
#define MAXDET     100

#define BLOCK      512
#define ITEMS      20                 // N <= 512*20 = 10240
#define NBINS      512
#define KCAP       1024               // collected-candidate capacity
#define MINB16     15692              // (bits(0.05f) >> 16)

// per-(b,c,m) kept score + box; flag for fallback. Sized for B<=4, C<=128.
__device__ float  g_sc[4 * 128 * MAXDET];
__device__ float4 g_bx[4 * 128 * MAXDET];
__device__ int    g_flag[4 * 128];

// ---- packed key: (orderable score bits << 32) | ~idx ----
// max(key) => max score, ties toward LOWEST index (matches jnp.argmax / top_k).
__device__ __forceinline__ unsigned long long packKey(float s, unsigned idx) {
    unsigned u = __float_as_uint(s);
    u = (u & 0x80000000u) ? ~u : (u | 0x80000000u);
    return ((unsigned long long)u << 32) | (unsigned)(~idx);
}
__device__ __forceinline__ float keyScore(unsigned long long k) {
    unsigned u = (unsigned)(k >> 32);
    u = (u & 0x80000000u) ? (u & 0x7FFFFFFFu) : ~u;
    return __uint_as_float(u);
}
__device__ __forceinline__ unsigned keyIdx(unsigned long long k) {
    return ~(unsigned)(k & 0xFFFFFFFFu);
}

// exact equivalent of RN(inter/u) > 0.5 for u >= ~1 (areas >= 1 here):
// inter/u > 0.5 + 2^-25  <=>  (inter - 0.5u) > 2^-25 * u, lhs exact via FMA.
__device__ __forceinline__ bool iouGtHalf(float inter, float u) {
    return fmaf(-0.5f, u, inter) > 2.9802322387695312e-08f * u;
}

__device__ __forceinline__ int binOf(float sc) {  // sc > 0.05 assumed
    int b = (int)(__float_as_uint(sc) >> 16) - MINB16;
    return b > (NBINS - 1) ? (NBINS - 1) : b;
}

// ================= Kernel 1: select + sort + warp-greedy NMS per (b,c) ========
__global__ void __launch_bounds__(BLOCK)
select_nms_kernel(const float4* __restrict__ boxes, const float* __restrict__ cls,
                  int N, int C) {
    __shared__ int                 S[NBINS];        // hist -> suffix counts
    __shared__ unsigned long long  key[KCAP];
    __shared__ float4              cbox[KCAP];
    __shared__ int                 s_piv, s_ctr, s_kept;

    const int c = blockIdx.x;
    const int b = blockIdx.y;
    const int t = threadIdx.x;
    const int bc = b * C + c;
    const int base = bc * MAXDET;
    const float4* bp = boxes + (size_t)b * N;
    const float*  cp = cls + ((size_t)b * N) * C + c;

    S[t] = 0;
    __syncthreads();

    // pass 1: load scores into regs + histogram
    float sc[ITEMS];
    #pragma unroll
    for (int j = 0; j < ITEMS; j++) {
        int i = j * BLOCK + t;
        sc[j] = (i < N) ? cp[(size_t)i * C] : 0.0f;
        if (sc[j] > SCORE_TH) atomicAdd(&S[binOf(sc[j])], 1);
    }
    __syncthreads();

    // suffix scan (count of values in bins >= t)
    #pragma unroll
    for (int off = 1; off < NBINS; off <<= 1) {
        int u = (t + off < NBINS) ? S[t + off] : 0;
        __syncthreads();
        S[t] += u;
        __syncthreads();
    }
    const int total = S[0];
    if (t == 0) g_flag[bc] = 0;

    if (total == 0) {
        for (int mm = t; mm < MAXDET; mm += BLOCK) g_sc[base + mm] = NEG;
        return;
    }
    const int target = total < 512 ? total : 512;
    if (S[t] >= target && (t == NBINS - 1 || S[t + 1] < target)) s_piv = t;
    if (t == 0) s_ctr = 0;
    __syncthreads();
    const int piv = s_piv;
    const int cnt = S[piv];

    if (cnt > KCAP) {               // can't hold the minimal superset -> fallback
        if (t == 0) g_flag[bc] = 1;
        return;
    }

    // collect candidates in bins >= piv
    #pragma unroll
    for (int j = 0; j < ITEMS; j++) {
        if (sc[j] > SCORE_TH && binOf(sc[j]) >= piv) {
            int pos = atomicAdd(&s_ctr, 1);
            key[pos] = packKey(sc[j], (unsigned)(j * BLOCK + t));
        }
    }
    __syncthreads();
    for (int p = cnt + t; p < KCAP; p += BLOCK) key[p] = 0ULL;
    __syncthreads();

    // bitonic sort descending, KCAP elems, BLOCK threads (1 pair each)
    #pragma unroll 1
    for (int k = 2; k <= KCAP; k <<= 1) {
        for (int jj = k >> 1; jj > 0; jj >>= 1) {
            int idx  = ((t & ~(jj - 1)) << 1) | (t & (jj - 1));
            int part = idx | jj;
            unsigned long long a = key[idx], bb = key[part];
            bool desc = (idx & k) == 0;
            if (desc ? (a < bb) : (a > bb)) { key[idx] = bb; key[part] = a; }
            __syncthreads();
        }
    }

    // gather candidate boxes in sorted order
    for (int p = t; p < cnt; p += BLOCK) cbox[p] = bp[keyIdx(key[p])];
    __syncthreads();

    // warp 0: greedy scan. kept boxes live in registers, 4 slots/lane (cap 128).
    if (t < 32) {
        const float4 DUMMY = make_float4(2e9f, 2e9f, 2e9f, 2e9f);
        float4 kb0 = DUMMY, kb1 = DUMMY, kb2 = DUMMY, kb3 = DUMMY;
        float  ka0 = 0.f, ka1 = 0.f, ka2 = 0.f, ka3 = 0.f;
        int kept = 0;
        for (int i = 0; i < cnt && kept < MAXDET; i++) {
            unsigned long long kk = key[i];
            float4 cb = cbox[i];
            float a1 = (cb.z - cb.x) * (cb.w - cb.y);
            bool supp = false;
            {
                float ix1, iy1, ix2, iy2, dx, dy, inter, u;
                ix1 = fmaxf(cb.x, kb0.x); iy1 = fmaxf(cb.y, kb0.y);
                ix2 = fminf(cb.z, kb0.z); iy2 = fminf(cb.w, kb0.w);
                dx = fmaxf(ix2 - ix1, 0.f); dy = fmaxf(iy2 - iy1, 0.f);
                inter = dx * dy; u = fmaxf(a1 + ka0 - inter, 1e-8f);
                supp |= iouGtHalf(inter, u);
                ix1 = fmaxf(cb.x, kb1.x); iy1 = fmaxf(cb.y, kb1.y);
                ix2 = fminf(cb.z, kb1.z); iy2 = fminf(cb.w, kb1.w);
                dx = fmaxf(ix2 - ix1, 0.f); dy = fmaxf(iy2 - iy1, 0.f);
                inter = dx * dy; u = fmaxf(a1 + ka1 - inter, 1e-8f);
                supp |= iouGtHalf(inter, u);
                ix1 = fmaxf(cb.x, kb2.x); iy1 = fmaxf(cb.y, kb2.y);
                ix2 = fminf(cb.z, kb2.z); iy2 = fminf(cb.w, kb2.w);
                dx = fmaxf(ix2 - ix1, 0.f); dy = fmaxf(iy2 - iy1, 0.f);
                inter = dx * dy; u = fmaxf(a1 + ka2 - inter, 1e-8f);
                supp |= iouGtHalf(inter, u);
                ix1 = fmaxf(cb.x, kb3.x); iy1 = fmaxf(cb.y, kb3.y);
                ix2 = fminf(cb.z, kb3.z); iy2 = fminf(cb.w, kb3.w);
                dx = fmaxf(ix2 - ix1, 0.f); dy = fmaxf(iy2 - iy1, 0.f);
                inter = dx * dy; u = fmaxf(a1 + ka3 - inter, 1e-8f);
                supp |= iouGtHalf(inter, u);
            }
            if (!__any_sync(0xFFFFFFFFu, supp)) {
                if (t == (kept & 31)) {
                    int slot = kept >> 5;
                    if      (slot == 0) { kb0 = cb; ka0 = a1; }
                    else if (slot == 1) { kb1 = cb; ka1 = a1; }
                    else if (slot == 2) { kb2 = cb; ka2 = a1; }
                    else                { kb3 = cb; ka3 = a1; }
                }
                if (t == 0) { g_sc[base + kept] = keyScore(kk); g_bx[base + kept] = cb; }
                kept++;
            }
        }
        if (t == 0) {
            s_kept = kept;
            if (kept < MAXDET && total > cnt) g_flag[bc] = 1;  // insufficient scan
        }
    }
    __syncthreads();
    int kept = s_kept;
    if (kept < MAXDET && total <= cnt) {      // legitimately exhausted
        for (int mm = kept + t; mm < MAXDET; mm += BLOCK) g_sc[base + mm] = NEG;
    }
    // if flagged, fallback kernel rewrites the whole class
}

// ============ Kernel 2: guaranteed-correct fallback (rarely/never runs) =======
__shared__ unsigned long long red_fb[17];
__device__ __forceinline__ unsigned long long blockKeyMax(unsigned long long k) {
    int lane = threadIdx.x & 31;
    int wid  = threadIdx.x >> 5;
    #pragma unroll
    for (int o = 16; o > 0; o >>= 1) {
        unsigned long long other = __shfl_down_sync(0xFFFFFFFFu, k, o);
        if (other > k) k = other;
    }
    if (lane == 0) red_fb[wid] = k;
    __syncthreads();
    if (wid == 0) {
        unsigned long long v = red_fb[lane & 15];
        #pragma unroll
        for (int o = 8; o > 0; o >>= 1) {
            unsigned long long other = __shfl_down_sync(0xFFFFFFFFu, v, o);
            if (other > v) v = other;
        }
        if (lane == 0) red_fb[16] = v;
    }
    __syncthreads();
    unsigned long long r = red_fb[16];
    __syncthreads();
    return r;
}

__global__ void __launch_bounds__(BLOCK)
fallback_nms_kernel(const float4* __restrict__ boxes, const float* __restrict__ cls,
                    int N, int C) {
    const int c = blockIdx.x;
    const int b = blockIdx.y;
    const int bc = b * C + c;
    if (g_flag[bc] == 0) return;
    const int t = threadIdx.x;
    const float4* bp = boxes + (size_t)b * N;
    const float*  cp = cls + ((size_t)b * N) * C + c;

    float s[ITEMS], a2[ITEMS];
    #pragma unroll
    for (int j = 0; j < ITEMS; j++) {
        int i = j * BLOCK + t;
        if (i < N) {
            float4 b4 = bp[i];
            a2[j] = (b4.z - b4.x) * (b4.w - b4.y);
            float v = cp[(size_t)i * C];
            s[j] = (v > SCORE_TH) ? v : NEG;
        } else { a2[j] = 0.f; s[j] = -3.402823466e+38f; }
    }
    const int base = bc * MAXDET;
    for (int m = 0; m < MAXDET; m++) {
        float bm = s[0]; int bj = 0;
        #pragma unroll
        for (int j = 1; j < ITEMS; j++) if (s[j] > bm) { bm = s[j]; bj = j; }
        unsigned long long k = blockKeyMax(packKey(bm, (unsigned)(bj * BLOCK + t)));
        float bscore = keyScore(k);
        if (!(bscore > SCORE_TH)) {
            for (int mm = m + t; mm < MAXDET; mm += BLOCK) g_sc[base + mm] = NEG;
            return;
        }
        unsigned bidx = keyIdx(k);
        float4 B0 = bp[bidx];                 // L2 broadcast
        if (t == 0) { g_sc[base + m] = bscore; g_bx[base + m] = B0; }
        float a1 = (B0.z - B0.x) * (B0.w - B0.y);
        #pragma unroll
        for (int j = 0; j < ITEMS; j++) {
            int i = j * BLOCK + t;
            float4 bb = (i < N) ? bp[i] : make_float4(0.f, 0.f, 0.f, 0.f);
            float ix1 = fmaxf(B0.x, bb.x), iy1 = fmaxf(B0.y, bb.y);
            float ix2 = fminf(B0.z, bb.z), iy2 = fminf(B0.w, bb.w);
            float inter = fmaxf(ix2 - ix1, 0.f) * fmaxf(iy2 - iy1, 0.f);
            float u = fmaxf(a1 + a2[j] - inter, 1e-8f);
            if (iouGtHalf(inter, u)) s[j] = NEG;
        }
    }
}

// ======== Kernel 3: per-image 80-way merge of sorted class lists (top-100) ====
__global__ void __launch_bounds__(128)
merge_kernel(float* __restrict__ out, int B, int C) {
    __shared__ float ssc[128 * MAXDET];          // C*M scores (C<=128)
    __shared__ unsigned long long swin[MAXDET];
    const int b = blockIdx.x;
    const int t = threadIdx.x;
    const int CM = C * MAXDET;
    const int base = b * CM;

    for (int i = t; i < CM; i += 128) ssc[i] = g_sc[base + i];
    __syncthreads();

    if (t < 32) {
        // lane owns classes t, t+32, t+64 (valid if < C)
        int c0 = t, c1 = t + 32, c2 = t + 64;
        int p0 = 0, p1 = 0, p2 = 0;
        unsigned long long h0 = (c0 < C) ? packKey(ssc[c0 * MAXDET], c0 * MAXDET) : 0ULL;
        unsigned long long h1 = (c1 < C) ? packKey(ssc[c1 * MAXDET], c1 * MAXDET) : 0ULL;
        unsigned long long h2 = (c2 < C) ? packKey(ssc[c2 * MAXDET], c2 * MAXDET) : 0ULL;
        for (int r = 0; r < MAXDET; r++) {
            unsigned long long k = h0;
            if (h1 > k) k = h1;
            if (h2 > k) k = h2;
            #pragma unroll
            for (int o = 16; o > 0; o >>= 1) {
                unsigned long long other = __shfl_down_sync(0xFFFFFFFFu, k, o);
                if (other > k) k = other;
            }
            k = __shfl_sync(0xFFFFFFFFu, k, 0);
            if (k == h0 && k) { p0++; h0 = (p0 < MAXDET) ? packKey(ssc[c0 * MAXDET + p0], c0 * MAXDET + p0) : 0ULL; }
            else if (k == h1 && k) { p1++; h1 = (p1 < MAXDET) ? packKey(ssc[c1 * MAXDET + p1], c1 * MAXDET + p1) : 0ULL; }
            else if (k == h2 && k) { p2++; h2 = (p2 < MAXDET) ? packKey(ssc[c2 * MAXDET + p2], c2 * MAXDET + p2) : 0ULL; }
            if (t == 0) swin[r] = k;
        }
    }
    __syncthreads();

    float* oBoxes  = out;
    float* oScores = out + (size_t)B * MAXDET * 4;
    float* oLabels = out + (size_t)B * MAXDET * 5;
    if (t < MAXDET) {
        unsigned long long k = swin[t];
        float sc = keyScore(k);
        unsigned idx = keyIdx(k);
        float bx = -1.f, by = -1.f, bz = -1.f, bw = -1.f, so = -1.f, lab = -1.f;
        if (k != 0ULL && sc > SCORE_TH) {
            float4 bb = g_bx[base + idx];
            bx = bb.x; by = bb.y; bz = bb.z; bw = bb.w;
            so = sc; lab = (float)(idx / MAXDET);
        }
        float* ob = oBoxes + ((size_t)b * MAXDET + t) * 4;
        ob[0] = bx; ob[1] = by; ob[2] = bz; ob[3] = bw;
        oScores[b * MAXDET + t] = so;
        oLabels[b * MAXDET + t] = lab;
    }
}

extern "C" void kernel_launch(void* const* d_in, const int* in_sizes, int n_in,
                              void* d_out, int out_size) {
    const float4* boxes = (const float4*)d_in[0];   // (B, N, 4) f32
    const float*  cls   = (const float*)d_in[1];    // (B, N, C) f32
    float*        out   = (float*)d_out;

    int B = out_size / (6 * MAXDET);
    if (B < 1) B = 1;
    int N = in_sizes[0] / (4 * B);
    int C = in_sizes[1] / (B * N);

    if (N > BLOCK * ITEMS || C > 96 || B * C > 4 * 128) return;  // bench: B=2,N=10000,C=80

    dim3 grid(C, B);
    select_nms_kernel<<<grid, BLOCK>>>(boxes, cls, N, C);
    fallback_nms_kernel<<<grid, BLOCK>>>(boxes, cls, N, C);
    merge_kernel<<<B, 128>>>(out, B, C);
}

// round 5
// speedup vs baseline: 16.3980x; 1.3040x over previous
#include <cuda_runtime.h>
#include <math.h>

#define NEG        (-1.0e9f)
#define SCORE_TH   (0.05f)
#define MAXDET     100

#define NBINS1     768                // (bits>>16) - MINB16; score 1.0 -> bin 564 (no clamp needed)
#define NBINS2     512                // bits[7:16) within one level-1 bin
#define MINB16     15692              // bits(0.05f) >> 16
#define KCAP       256                // select/topk candidate capacity
#define TARGET     224                // select candidate target
#define TB         256
#define FBLOCK     512
#define FITEMS     20                 // N <= 512*20
#define ТITEMS     16
#define TITEMS     16                 // C*M <= 512*16
#define TROWS      64

#define MAXB       4
#define MAXC       96
#define MAXN       10240

__device__ float  g_tcls[MAXB * MAXC * MAXN];   // (B,C,N) transposed scores
__device__ float  g_sc[MAXB * MAXC * MAXDET];
__device__ float4 g_bx[MAXB * MAXC * MAXDET];
__device__ int    g_flag[MAXB * MAXC];
__device__ int    g_tkflag[MAXB];

__device__ __forceinline__ unsigned long long packKey(float s, unsigned idx) {
    unsigned u = __float_as_uint(s);
    u = (u & 0x80000000u) ? ~u : (u | 0x80000000u);
    return ((unsigned long long)u << 32) | (unsigned)(~idx);
}
__device__ __forceinline__ float keyScore(unsigned long long k) {
    unsigned u = (unsigned)(k >> 32);
    u = (u & 0x80000000u) ? (u & 0x7FFFFFFFu) : ~u;
    return __uint_as_float(u);
}
__device__ __forceinline__ unsigned keyIdx(unsigned long long k) {
    return ~(unsigned)(k & 0xFFFFFFFFu);
}
// exact equivalent of RN(inter/u) > 0.5 for u >= ~1 (areas >= 1 here)
__device__ __forceinline__ bool iouGtHalf(float inter, float u) {
    return fmaf(-0.5f, u, inter) > 2.9802322387695312e-08f * u;
}
__device__ __forceinline__ int binOf1(float sc) {   // sc > 0.05
    int b = (int)(__float_as_uint(sc) >> 16) - MINB16;
    return b > (NBINS1 - 1) ? (NBINS1 - 1) : b;
}
__device__ __forceinline__ int binOf2(float sc) {
    return (int)((__float_as_uint(sc) >> 7) & 0x1FFu);
}

// ===================== Kernel 0: transpose (B,N,C)->(B,C,N) ==================
__global__ void __launch_bounds__(TB)
transpose_kernel(const float* __restrict__ cls, int N, int C) {
    __shared__ float tile[TROWS * MAXC];
    const int b  = blockIdx.y;
    const int i0 = blockIdx.x * TROWS;
    const int t  = threadIdx.x;
    int rows = N - i0; if (rows > TROWS) rows = TROWS;
    const int n_e = rows * C;
    const float* src = cls + (size_t)b * N * C + (size_t)i0 * C;
    for (int e = t; e < n_e; e += TB) tile[e] = src[e];
    __syncthreads();
    for (int e = t; e < n_e; e += TB) {
        int c = e / rows, r = e - c * rows;
        g_tcls[((size_t)(b * MAXC + c)) * MAXN + i0 + r] = tile[r * C + c];
    }
}

// ======= Kernel 1: 2-level radix select + bitonic + warp-greedy NMS ==========
__global__ void __launch_bounds__(TB)
select_nms_kernel(const float4* __restrict__ boxes, int N, int C) {
    __shared__ int                S[NBINS1];
    __shared__ int                S2[NBINS2];
    __shared__ unsigned long long key[KCAP];
    __shared__ float4             cbox[KCAP];
    __shared__ int                s_piv1, s_piv2, s_ctr, s_kept;

    const int c = blockIdx.x;
    const int b = blockIdx.y;
    const int t = threadIdx.x;
    const int bc = b * C + c;
    const int base = bc * MAXDET;
    const float*  cp = g_tcls + ((size_t)(b * MAXC + c)) * MAXN;
    const float4* bp = boxes + (size_t)b * N;

    S[t] = 0; S[t + TB] = 0; S[t + 2 * TB] = 0;
    if (t == 0) { s_ctr = 0; g_flag[bc] = 0; }
    __syncthreads();

    for (int i = t; i < N; i += TB) {
        float v = cp[i];
        if (v > SCORE_TH) atomicAdd(&S[binOf1(v)], 1);
    }
    __syncthreads();

    // suffix scan over NBINS1=768 (3 bins/thread)
    #pragma unroll
    for (int off = 1; off < NBINS1; off <<= 1) {
        int a0 = (t + off < NBINS1) ? S[t + off] : 0;
        int a1 = (t + TB + off < NBINS1) ? S[t + TB + off] : 0;
        int a2 = (t + 2 * TB + off < NBINS1) ? S[t + 2 * TB + off] : 0;
        __syncthreads();
        S[t] += a0; S[t + TB] += a1; S[t + 2 * TB] += a2;
        __syncthreads();
    }
    const int total = S[0];
    if (total == 0) {
        for (int mm = t; mm < MAXDET; mm += TB) g_sc[base + mm] = NEG;
        return;
    }
    const int target = total < TARGET ? total : TARGET;
    #pragma unroll
    for (int h = 0; h < 3; h++) {
        int p = t + h * TB;
        if (S[p] >= target && (p == NBINS1 - 1 || S[p + 1] < target)) s_piv1 = p;
    }
    __syncthreads();
    const int piv1 = s_piv1;
    const int cnt1 = S[piv1];
    const int above = (piv1 + 1 < NBINS1) ? S[piv1 + 1] : 0;
    const bool use2 = (cnt1 > KCAP);
    int piv2 = 0;
    int cnt  = cnt1;

    if (use2) {
        S2[t] = 0; S2[t + TB] = 0;
        __syncthreads();
        for (int i = t; i < N; i += TB) {
            float v = cp[i];
            if (v > SCORE_TH && binOf1(v) == piv1) atomicAdd(&S2[binOf2(v)], 1);
        }
        __syncthreads();
        #pragma unroll
        for (int off = 1; off < NBINS2; off <<= 1) {
            int a0 = (t + off < NBINS2) ? S2[t + off] : 0;
            int a1 = (t + TB + off < NBINS2) ? S2[t + TB + off] : 0;
            __syncthreads();
            S2[t] += a0; S2[t + TB] += a1;
            __syncthreads();
        }
        const int need = target - above;     // in [1, target]
        #pragma unroll
        for (int h = 0; h < 2; h++) {
            int p = t + h * TB;
            if (S2[p] >= need && (p == NBINS2 - 1 || S2[p + 1] < need)) s_piv2 = p;
        }
        __syncthreads();
        piv2 = s_piv2;
        cnt  = above + S2[piv2];
        if (cnt > KCAP) { if (t == 0) g_flag[bc] = 1; return; }
    }

    // collect
    for (int i = t; i < N; i += TB) {
        float v = cp[i];
        if (v > SCORE_TH) {
            int b1 = binOf1(v);
            if (b1 > piv1 || (b1 == piv1 && (!use2 || binOf2(v) >= piv2))) {
                int pos = atomicAdd(&s_ctr, 1);
                key[pos] = packKey(v, (unsigned)i);
            }
        }
    }
    __syncthreads();
    for (int p = cnt + t; p < KCAP; p += TB) key[p] = 0ULL;
    __syncthreads();

    // bitonic sort descending, 256 elems, 128 pairs
    #pragma unroll 1
    for (int k = 2; k <= KCAP; k <<= 1) {
        for (int jj = k >> 1; jj > 0; jj >>= 1) {
            if (t < KCAP / 2) {
                int idx  = ((t & ~(jj - 1)) << 1) | (t & (jj - 1));
                int part = idx | jj;
                unsigned long long a = key[idx], bb = key[part];
                if ((idx & k) == 0 ? (a < bb) : (a > bb)) { key[idx] = bb; key[part] = a; }
            }
            __syncthreads();
        }
    }
    if (t < cnt) cbox[t] = bp[keyIdx(key[t])];
    __syncthreads();

    // warp 0: greedy scan; kept boxes in registers, 4 slots/lane (cap 128)
    if (t < 32) {
        const float4 DUMMY = make_float4(2e9f, 2e9f, 2e9f, 2e9f);
        float4 kb0 = DUMMY, kb1 = DUMMY, kb2 = DUMMY, kb3 = DUMMY;
        float  ka0 = 0.f, ka1 = 0.f, ka2 = 0.f, ka3 = 0.f;
        int kept = 0;
        for (int i = 0; i < cnt && kept < MAXDET; i++) {
            unsigned long long kk = key[i];
            float4 cb = cbox[i];
            float a1 = (cb.z - cb.x) * (cb.w - cb.y);
            float ix1, iy1, ix2, iy2, dx, dy, inter, u;
            bool supp = false;
            ix1 = fmaxf(cb.x, kb0.x); iy1 = fmaxf(cb.y, kb0.y);
            ix2 = fminf(cb.z, kb0.z); iy2 = fminf(cb.w, kb0.w);
            dx = fmaxf(ix2 - ix1, 0.f); dy = fmaxf(iy2 - iy1, 0.f);
            inter = dx * dy; u = fmaxf(a1 + ka0 - inter, 1e-8f);
            supp |= iouGtHalf(inter, u);
            ix1 = fmaxf(cb.x, kb1.x); iy1 = fmaxf(cb.y, kb1.y);
            ix2 = fminf(cb.z, kb1.z); iy2 = fminf(cb.w, kb1.w);
            dx = fmaxf(ix2 - ix1, 0.f); dy = fmaxf(iy2 - iy1, 0.f);
            inter = dx * dy; u = fmaxf(a1 + ka1 - inter, 1e-8f);
            supp |= iouGtHalf(inter, u);
            ix1 = fmaxf(cb.x, kb2.x); iy1 = fmaxf(cb.y, kb2.y);
            ix2 = fminf(cb.z, kb2.z); iy2 = fminf(cb.w, kb2.w);
            dx = fmaxf(ix2 - ix1, 0.f); dy = fmaxf(iy2 - iy1, 0.f);
            inter = dx * dy; u = fmaxf(a1 + ka2 - inter, 1e-8f);
            supp |= iouGtHalf(inter, u);
            ix1 = fmaxf(cb.x, kb3.x); iy1 = fmaxf(cb.y, kb3.y);
            ix2 = fminf(cb.z, kb3.z); iy2 = fminf(cb.w, kb3.w);
            dx = fmaxf(ix2 - ix1, 0.f); dy = fmaxf(iy2 - iy1, 0.f);
            inter = dx * dy; u = fmaxf(a1 + ka3 - inter, 1e-8f);
            supp |= iouGtHalf(inter, u);
            if (!__any_sync(0xFFFFFFFFu, supp)) {
                if (t == (kept & 31)) {
                    int slot = kept >> 5;
                    if      (slot == 0) { kb0 = cb; ka0 = a1; }
                    else if (slot == 1) { kb1 = cb; ka1 = a1; }
                    else if (slot == 2) { kb2 = cb; ka2 = a1; }
                    else                { kb3 = cb; ka3 = a1; }
                }
                if (t == 0) { g_sc[base + kept] = keyScore(kk); g_bx[base + kept] = cb; }
                kept++;
            }
        }
        if (t == 0) {
            s_kept = kept;
            if (kept < MAXDET && total > cnt) g_flag[bc] = 1;
        }
    }
    __syncthreads();
    int kept = s_kept;
    if (kept < MAXDET && total <= cnt) {
        for (int mm = kept + t; mm < MAXDET; mm += TB) g_sc[base + mm] = NEG;
    }
}

// =================== exact block argmax helper (512 thr) ====================
__device__ __forceinline__ unsigned long long blockKeyMax(unsigned long long k,
                                                          unsigned long long* red) {
    int lane = threadIdx.x & 31;
    int wid  = threadIdx.x >> 5;
    #pragma unroll
    for (int o = 16; o > 0; o >>= 1) {
        unsigned long long other = __shfl_down_sync(0xFFFFFFFFu, k, o);
        if (other > k) k = other;
    }
    if (lane == 0) red[wid] = k;
    __syncthreads();
    if (wid == 0) {
        unsigned long long v = red[lane & 15];
        #pragma unroll
        for (int o = 8; o > 0; o >>= 1) {
            unsigned long long other = __shfl_down_sync(0xFFFFFFFFu, v, o);
            if (other > v) v = other;
        }
        if (lane == 0) red[16] = v;
    }
    __syncthreads();
    unsigned long long r = red[16];
    __syncthreads();
    return r;
}

// ============ Kernel 2: exact NMS fallback (normally no-op) ==================
__global__ void __launch_bounds__(FBLOCK)
fallback_nms_kernel(const float4* __restrict__ boxes, int N, int C) {
    __shared__ unsigned long long red[17];
    const int c = blockIdx.x;
    const int b = blockIdx.y;
    const int bc = b * C + c;
    if (g_flag[bc] == 0) return;
    const int t = threadIdx.x;
    const float4* bp = boxes + (size_t)b * N;
    const float*  cp = g_tcls + ((size_t)(b * MAXC + c)) * MAXN;

    float s[FITEMS], a2[FITEMS];
    #pragma unroll
    for (int j = 0; j < FITEMS; j++) {
        int i = j * FBLOCK + t;
        if (i < N) {
            float4 b4 = bp[i];
            a2[j] = (b4.z - b4.x) * (b4.w - b4.y);
            float v = cp[i];
            s[j] = (v > SCORE_TH) ? v : NEG;
        } else { a2[j] = 0.f; s[j] = -3.402823466e+38f; }
    }
    const int base = bc * MAXDET;
    for (int m = 0; m < MAXDET; m++) {
        float bm = s[0]; int bj = 0;
        #pragma unroll
        for (int j = 1; j < FITEMS; j++) if (s[j] > bm) { bm = s[j]; bj = j; }
        unsigned long long k = blockKeyMax(packKey(bm, (unsigned)(bj * FBLOCK + t)), red);
        float bscore = keyScore(k);
        if (!(bscore > SCORE_TH)) {
            for (int mm = m + t; mm < MAXDET; mm += FBLOCK) g_sc[base + mm] = NEG;
            return;
        }
        unsigned bidx = keyIdx(k);
        float4 B0 = bp[bidx];
        if (t == 0) { g_sc[base + m] = bscore; g_bx[base + m] = B0; }
        float a1 = (B0.z - B0.x) * (B0.w - B0.y);
        #pragma unroll
        for (int j = 0; j < FITEMS; j++) {
            int i = j * FBLOCK + t;
            float4 bb = (i < N) ? bp[i] : make_float4(0.f, 0.f, 0.f, 0.f);
            float ix1 = fmaxf(B0.x, bb.x), iy1 = fmaxf(B0.y, bb.y);
            float ix2 = fminf(B0.z, bb.z), iy2 = fminf(B0.w, bb.w);
            float inter = fmaxf(ix2 - ix1, 0.f) * fmaxf(iy2 - iy1, 0.f);
            float u = fmaxf(a1 + a2[j] - inter, 1e-8f);
            if (iouGtHalf(inter, u)) s[j] = NEG;
        }
    }
}

// ======= Kernel 3: per-image exact top-100 via 2-level radix select ==========
__global__ void __launch_bounds__(TB)
topk_kernel(float* __restrict__ out, int B, int C) {
    __shared__ int                S[NBINS1];
    __shared__ int                S2[NBINS2];
    __shared__ unsigned long long key[KCAP];
    __shared__ int                s_piv1, s_piv2, s_ctr;

    const int b = blockIdx.x;
    const int t = threadIdx.x;
    const int CM = C * MAXDET;
    const int base = b * CM;
    const float* sp = g_sc + base;

    S[t] = 0; S[t + TB] = 0; S[t + 2 * TB] = 0;
    if (t == 0) { s_ctr = 0; g_tkflag[b] = 0; }
    __syncthreads();
    for (int i = t; i < CM; i += TB) {
        float v = sp[i];
        if (v > SCORE_TH) atomicAdd(&S[binOf1(v)], 1);
    }
    __syncthreads();
    #pragma unroll
    for (int off = 1; off < NBINS1; off <<= 1) {
        int a0 = (t + off < NBINS1) ? S[t + off] : 0;
        int a1 = (t + TB + off < NBINS1) ? S[t + TB + off] : 0;
        int a2 = (t + 2 * TB + off < NBINS1) ? S[t + 2 * TB + off] : 0;
        __syncthreads();
        S[t] += a0; S[t + TB] += a1; S[t + 2 * TB] += a2;
        __syncthreads();
    }
    const int total = S[0];
    int cnt = 0;
    if (total > 0) {
        const int target = total < MAXDET ? total : MAXDET;
        #pragma unroll
        for (int h = 0; h < 3; h++) {
            int p = t + h * TB;
            if (S[p] >= target && (p == NBINS1 - 1 || S[p + 1] < target)) s_piv1 = p;
        }
        __syncthreads();
        const int piv1 = s_piv1;
        const int cnt1 = S[piv1];
        const int above = (piv1 + 1 < NBINS1) ? S[piv1 + 1] : 0;
        const bool use2 = (cnt1 > KCAP);
        int piv2 = 0;
        cnt = cnt1;
        if (use2) {
            S2[t] = 0; S2[t + TB] = 0;
            __syncthreads();
            for (int i = t; i < CM; i += TB) {
                float v = sp[i];
                if (v > SCORE_TH && binOf1(v) == piv1) atomicAdd(&S2[binOf2(v)], 1);
            }
            __syncthreads();
            #pragma unroll
            for (int off = 1; off < NBINS2; off <<= 1) {
                int a0 = (t + off < NBINS2) ? S2[t + off] : 0;
                int a1 = (t + TB + off < NBINS2) ? S2[t + TB + off] : 0;
                __syncthreads();
                S2[t] += a0; S2[t + TB] += a1;
                __syncthreads();
            }
            const int need = target - above;
            #pragma unroll
            for (int h = 0; h < 2; h++) {
                int p = t + h * TB;
                if (S2[p] >= need && (p == NBINS2 - 1 || S2[p + 1] < need)) s_piv2 = p;
            }
            __syncthreads();
            piv2 = s_piv2;
            cnt  = above + S2[piv2];
            if (cnt > KCAP) { if (t == 0) g_tkflag[b] = 1; return; }
        }
        for (int i = t; i < CM; i += TB) {
            float v = sp[i];
            if (v > SCORE_TH) {
                int b1 = binOf1(v);
                if (b1 > piv1 || (b1 == piv1 && (!use2 || binOf2(v) >= piv2))) {
                    int pos = atomicAdd(&s_ctr, 1);
                    key[pos] = packKey(v, (unsigned)i);
                }
            }
        }
    }
    __syncthreads();
    for (int p = cnt + t; p < KCAP; p += TB) key[p] = 0ULL;
    __syncthreads();
    #pragma unroll 1
    for (int k = 2; k <= KCAP; k <<= 1) {
        for (int jj = k >> 1; jj > 0; jj >>= 1) {
            if (t < KCAP / 2) {
                int idx  = ((t & ~(jj - 1)) << 1) | (t & (jj - 1));
                int part = idx | jj;
                unsigned long long a = key[idx], bb = key[part];
                if ((idx & k) == 0 ? (a < bb) : (a > bb)) { key[idx] = bb; key[part] = a; }
            }
            __syncthreads();
        }
    }

    float* oBoxes  = out;
    float* oScores = out + (size_t)B * MAXDET * 4;
    float* oLabels = out + (size_t)B * MAXDET * 5;
    if (t < MAXDET) {
        float bx = -1.f, by = -1.f, bz = -1.f, bw = -1.f, so = -1.f, lab = -1.f;
        if (t < cnt) {
            unsigned long long k = key[t];
            float sc = keyScore(k);
            unsigned idx = keyIdx(k);
            float4 bb = g_bx[base + idx];
            bx = bb.x; by = bb.y; bz = bb.z; bw = bb.w;
            so = sc; lab = (float)(idx / MAXDET);
        }
        float* ob = oBoxes + ((size_t)b * MAXDET + t) * 4;
        ob[0] = bx; ob[1] = by; ob[2] = bz; ob[3] = bw;
        oScores[b * MAXDET + t] = so;
        oLabels[b * MAXDET + t] = lab;
    }
}

// ====== Kernel 4: exact top-k fallback (iterative argmax; normally no-op) ====
__global__ void __launch_bounds__(FBLOCK)
topk_fallback_kernel(float* __restrict__ out, int B, int C) {
    __shared__ unsigned long long red[17];
    const int b = blockIdx.x;
    if (g_tkflag[b] == 0) return;
    const int t = threadIdx.x;
    const int CM = C * MAXDET;
    const int base = b * CM;

    unsigned long long key[TITEMS];
    #pragma unroll
    for (int j = 0; j < TITEMS; j++) {
        int i = j * FBLOCK + t;
        key[j] = (i < CM) ? packKey(g_sc[base + i], (unsigned)i) : 0ULL;
    }
    float* oBoxes  = out;
    float* oScores = out + (size_t)B * MAXDET * 4;
    float* oLabels = out + (size_t)B * MAXDET * 5;
    for (int r = 0; r < MAXDET; r++) {
        unsigned long long k0 = key[0];
        #pragma unroll
        for (int j = 1; j < TITEMS; j++) if (key[j] > k0) k0 = key[j];
        unsigned long long k = blockKeyMax(k0, red);
        #pragma unroll
        for (int j = 0; j < TITEMS; j++) if (key[j] == k) key[j] = 0ULL;
        if (t == 0) {
            float sc = keyScore(k);
            unsigned idx = keyIdx(k);
            float bx = -1.f, by = -1.f, bz = -1.f, bw = -1.f, so = -1.f, lab = -1.f;
            if (k != 0ULL && sc > SCORE_TH) {
                float4 bb = g_bx[base + idx];
                bx = bb.x; by = bb.y; bz = bb.z; bw = bb.w;
                so = sc; lab = (float)(idx / MAXDET);
            }
            float* ob = oBoxes + ((size_t)b * MAXDET + r) * 4;
            ob[0] = bx; ob[1] = by; ob[2] = bz; ob[3] = bw;
            oScores[b * MAXDET + r] = so;
            oLabels[b * MAXDET + r] = lab;
        }
    }
}

extern "C" void kernel_launch(void* const* d_in, const int* in_sizes, int n_in,
                              void* d_out, int out_size) {
    const float4* boxes = (const float4*)d_in[0];   // (B, N, 4) f32
    const float*  cls   = (const float*)d_in[1];    // (B, N, C) f32
    float*        out   = (float*)d_out;

    int B = out_size / (6 * MAXDET);
    if (B < 1) B = 1;
    int N = in_sizes[0] / (4 * B);
    int C = in_sizes[1] / (B * N);
    if (N > MAXN || C > MAXC || B > MAXB || C * MAXDET > FBLOCK * TITEMS) return;

    dim3 tgrid((N + TROWS - 1) / TROWS, B);
    transpose_kernel<<<tgrid, TB>>>(cls, N, C);
    dim3 grid(C, B);
    select_nms_kernel<<<grid, TB>>>(boxes, N, C);
    fallback_nms_kernel<<<grid, FBLOCK>>>(boxes, N, C);
    topk_kernel<<<B, TB>>>(out, B, C);
    topk_fallback_kernel<<<B, FBLOCK>>>(out, B, C);
}

// round 6
// speedup vs baseline: 18.0694x; 1.1019x over previous
#include <cuda_runtime.h>
#include <math.h>

#define NEG        (-1.0e9f)
#define SCORE_TH   (0.05f)
#define MAXDET     100

#define NBINS1     1024               // (bits>>16)-MINB16; score 1.0 -> bin 564
#define NBINS2     512                // bits[7:16) within one level-1 bin
#define MINB16     15692              // bits(0.05f) >> 16
#define KCAP       256                // select candidate capacity
#define TARGET     224                // select candidate target
#define KCAP2      128                // topk candidate capacity
#define SB         512                // select block
#define TB2        1024               // topk block
#define FBLOCK     512
#define FITEMS     20                 // N <= 512*20
#define TKITEMS    8                  // C*M <= 1024*8
#define TROWS      64
#define XB         256                // transpose block

#define MAXB       4
#define MAXC       96
#define MAXN       10240

__device__ float  g_tcls[MAXB * MAXC * MAXN];   // (B,C,N) transposed scores
__device__ float  g_sc[MAXB * MAXC * MAXDET];
__device__ float4 g_bx[MAXB * MAXC * MAXDET];
__device__ int    g_flag[MAXB * MAXC];

__device__ __forceinline__ unsigned long long packKey(float s, unsigned idx) {
    unsigned u = __float_as_uint(s);
    u = (u & 0x80000000u) ? ~u : (u | 0x80000000u);
    return ((unsigned long long)u << 32) | (unsigned)(~idx);
}
__device__ __forceinline__ float keyScore(unsigned long long k) {
    unsigned u = (unsigned)(k >> 32);
    u = (u & 0x80000000u) ? (u & 0x7FFFFFFFu) : ~u;
    return __uint_as_float(u);
}
__device__ __forceinline__ unsigned keyIdx(unsigned long long k) {
    return ~(unsigned)(k & 0xFFFFFFFFu);
}
// exact equivalent of RN(inter/u) > 0.5 for u >= ~1 (areas >= 1 here)
__device__ __forceinline__ bool iouGtHalf(float inter, float u) {
    return fmaf(-0.5f, u, inter) > 2.9802322387695312e-08f * u;
}
__device__ __forceinline__ int binOf1(float sc) {   // sc > 0.05
    int b = (int)(__float_as_uint(sc) >> 16) - MINB16;
    return b > (NBINS1 - 1) ? (NBINS1 - 1) : b;
}
__device__ __forceinline__ int binOf2(float sc) {
    return (int)((__float_as_uint(sc) >> 7) & 0x1FFu);
}

// ===================== Kernel 0: transpose (B,N,C)->(B,C,N) ==================
__global__ void __launch_bounds__(XB)
transpose_kernel(const float* __restrict__ cls, int N, int C) {
    __shared__ float tile[TROWS * MAXC];
    const int b  = blockIdx.y;
    const int i0 = blockIdx.x * TROWS;
    const int t  = threadIdx.x;
    int rows = N - i0; if (rows > TROWS) rows = TROWS;
    const int n_e = rows * C;
    const float* src = cls + (size_t)b * N * C + (size_t)i0 * C;
    if ((C & 3) == 0) {
        const float4* s4 = (const float4*)src;
        float4* t4 = (float4*)tile;
        for (int e = t; e < n_e / 4; e += XB) t4[e] = s4[e];
    } else {
        for (int e = t; e < n_e; e += XB) tile[e] = src[e];
    }
    __syncthreads();
    if (rows == TROWS) {
        for (int e = t; e < n_e; e += XB) {
            int c = e >> 6, r = e & 63;   // TROWS = 64
            g_tcls[((size_t)(b * MAXC + c)) * MAXN + i0 + r] = tile[r * C + c];
        }
    } else {
        for (int e = t; e < n_e; e += XB) {
            int c = e / rows, r = e - c * rows;
            g_tcls[((size_t)(b * MAXC + c)) * MAXN + i0 + r] = tile[r * C + c];
        }
    }
}

// ======= Kernel 1: 2-level radix select + bitonic + warp-greedy NMS ==========
__global__ void __launch_bounds__(SB)
select_nms_kernel(const float4* __restrict__ boxes, int N, int C) {
    __shared__ int                S[NBINS1];
    __shared__ int                S2[NBINS2];
    __shared__ unsigned long long key[KCAP];
    __shared__ float4             cbox[KCAP + 1];
    __shared__ float              carea[KCAP + 1];
    __shared__ int                wsum[16], wafter[16];
    __shared__ int                s_piv1, s_piv2, s_ctr, s_kept;

    const int c = blockIdx.x;
    const int b = blockIdx.y;
    const int t = threadIdx.x;
    const int lane = t & 31, wid = t >> 5;
    const int bc = b * C + c;
    const int base = bc * MAXDET;
    const float*  cp = g_tcls + ((size_t)(b * MAXC + c)) * MAXN;
    const float4* bp = boxes + (size_t)b * N;

    S[2 * t] = 0; S[2 * t + 1] = 0;
    S2[t] = 0;
    if (t == 0) { s_ctr = 0; g_flag[bc] = 0; }
    __syncthreads();

    for (int i = t; i < N; i += SB) {
        float v = cp[i];
        if (v > SCORE_TH) atomicAdd(&S[binOf1(v)], 1);
    }
    __syncthreads();

    // warp-segmented suffix scan over 1024 bins (2/thread, 16 warps)
    int b0 = S[2 * t], b1 = S[2 * t + 1];
    {
        int s = b0 + b1;
        #pragma unroll
        for (int o = 1; o < 32; o <<= 1) {
            int u = __shfl_down_sync(0xFFFFFFFFu, s, o);
            if (lane + o < 32) s += u;
        }
        if (lane == 0) wsum[wid] = s;
        __syncthreads();
        if (t < 32) {
            int v = (t < 16) ? wsum[t] : 0;
            #pragma unroll
            for (int o = 1; o < 16; o <<= 1) {
                int u = __shfl_down_sync(0xFFFFFFFFu, v, o);
                if (t + o < 32) v += u;
            }
            if (t < 16) wafter[t] = v - wsum[t];
        }
        __syncthreads();
        int T = s + wafter[wid];
        S[2 * t] = T;
        S[2 * t + 1] = T - b0;
    }
    __syncthreads();

    const int total = S[0];
    if (total == 0) {
        for (int mm = t; mm < MAXDET; mm += SB) g_sc[base + mm] = NEG;
        return;
    }
    const int target = total < TARGET ? total : TARGET;
    #pragma unroll
    for (int h = 0; h < 2; h++) {
        int p = t + h * SB;
        if (S[p] >= target && (p == NBINS1 - 1 || S[p + 1] < target)) s_piv1 = p;
    }
    __syncthreads();
    const int piv1 = s_piv1;
    const int cnt1 = S[piv1];
    const int above = (piv1 + 1 < NBINS1) ? S[piv1 + 1] : 0;
    const bool use2 = (cnt1 > KCAP);
    int piv2 = 0;
    int cnt  = cnt1;

    if (use2) {
        for (int i = t; i < N; i += SB) {
            float v = cp[i];
            if (v > SCORE_TH && binOf1(v) == piv1) atomicAdd(&S2[binOf2(v)], 1);
        }
        __syncthreads();
        int c0 = S2[t];
        {
            int s = c0;
            #pragma unroll
            for (int o = 1; o < 32; o <<= 1) {
                int u = __shfl_down_sync(0xFFFFFFFFu, s, o);
                if (lane + o < 32) s += u;
            }
            if (lane == 0) wsum[wid] = s;
            __syncthreads();
            if (t < 32) {
                int v = (t < 16) ? wsum[t] : 0;
                #pragma unroll
                for (int o = 1; o < 16; o <<= 1) {
                    int u = __shfl_down_sync(0xFFFFFFFFu, v, o);
                    if (t + o < 32) v += u;
                }
                if (t < 16) wafter[t] = v - wsum[t];
            }
            __syncthreads();
            S2[t] = s + wafter[wid];
        }
        __syncthreads();
        const int need = target - above;
        if (S2[t] >= need && (t == NBINS2 - 1 || S2[t + 1] < need)) s_piv2 = t;
        __syncthreads();
        piv2 = s_piv2;
        cnt  = above + S2[piv2];
        if (cnt > KCAP) { if (t == 0) g_flag[bc] = 1; return; }
    }

    // collect
    for (int i = t; i < N; i += SB) {
        float v = cp[i];
        if (v > SCORE_TH) {
            int b1v = binOf1(v);
            if (b1v > piv1 || (b1v == piv1 && (!use2 || binOf2(v) >= piv2))) {
                int pos = atomicAdd(&s_ctr, 1);
                key[pos] = packKey(v, (unsigned)i);
            }
        }
    }
    __syncthreads();
    for (int p = cnt + t; p < KCAP; p += SB) key[p] = 0ULL;
    __syncthreads();

    // bitonic sort descending, 256 elems, 128 pairs
    #pragma unroll 1
    for (int k = 2; k <= KCAP; k <<= 1) {
        for (int jj = k >> 1; jj > 0; jj >>= 1) {
            if (t < KCAP / 2) {
                int idx  = ((t & ~(jj - 1)) << 1) | (t & (jj - 1));
                int part = idx | jj;
                unsigned long long a = key[idx], bb = key[part];
                if ((idx & k) == 0 ? (a < bb) : (a > bb)) { key[idx] = bb; key[part] = a; }
            }
            __syncthreads();
        }
    }
    if (t < cnt) {
        float4 v = bp[keyIdx(key[t])];
        cbox[t] = v;
        carea[t] = (v.z - v.x) * (v.w - v.y);
    }
    if (t == cnt) {   // prefetch pad (cnt <= 256 < SB)
        cbox[cnt] = make_float4(2e9f, 2e9f, 2e9f, 2e9f);
        carea[cnt] = 0.f;
    }
    __syncthreads();

    // warp 0: greedy scan; kept boxes in registers, 4 slots/lane (cap 128)
    if (t < 32) {
        const float4 DUMMY = make_float4(2e9f, 2e9f, 2e9f, 2e9f);
        float4 kb0 = DUMMY, kb1 = DUMMY, kb2 = DUMMY, kb3 = DUMMY;
        float  ka0 = 0.f, ka1 = 0.f, ka2 = 0.f, ka3 = 0.f;
        int kept = 0;
        float4 cb = cbox[0];
        float  a1 = carea[0];
        for (int i = 0; i < cnt && kept < MAXDET; i++) {
            float4 nb = cbox[i + 1];      // software prefetch (padded)
            float  na = carea[i + 1];
            float ix1, iy1, ix2, iy2, dx, dy, inter, u;
            bool supp = false;
            ix1 = fmaxf(cb.x, kb0.x); iy1 = fmaxf(cb.y, kb0.y);
            ix2 = fminf(cb.z, kb0.z); iy2 = fminf(cb.w, kb0.w);
            dx = fmaxf(ix2 - ix1, 0.f); dy = fmaxf(iy2 - iy1, 0.f);
            inter = dx * dy; u = fmaxf(a1 + ka0 - inter, 1e-8f);
            supp |= iouGtHalf(inter, u);
            ix1 = fmaxf(cb.x, kb1.x); iy1 = fmaxf(cb.y, kb1.y);
            ix2 = fminf(cb.z, kb1.z); iy2 = fminf(cb.w, kb1.w);
            dx = fmaxf(ix2 - ix1, 0.f); dy = fmaxf(iy2 - iy1, 0.f);
            inter = dx * dy; u = fmaxf(a1 + ka1 - inter, 1e-8f);
            supp |= iouGtHalf(inter, u);
            ix1 = fmaxf(cb.x, kb2.x); iy1 = fmaxf(cb.y, kb2.y);
            ix2 = fminf(cb.z, kb2.z); iy2 = fminf(cb.w, kb2.w);
            dx = fmaxf(ix2 - ix1, 0.f); dy = fmaxf(iy2 - iy1, 0.f);
            inter = dx * dy; u = fmaxf(a1 + ka2 - inter, 1e-8f);
            supp |= iouGtHalf(inter, u);
            ix1 = fmaxf(cb.x, kb3.x); iy1 = fmaxf(cb.y, kb3.y);
            ix2 = fminf(cb.z, kb3.z); iy2 = fminf(cb.w, kb3.w);
            dx = fmaxf(ix2 - ix1, 0.f); dy = fmaxf(iy2 - iy1, 0.f);
            inter = dx * dy; u = fmaxf(a1 + ka3 - inter, 1e-8f);
            supp |= iouGtHalf(inter, u);
            if (!__any_sync(0xFFFFFFFFu, supp)) {
                if (t == (kept & 31)) {
                    int slot = kept >> 5;
                    if      (slot == 0) { kb0 = cb; ka0 = a1; }
                    else if (slot == 1) { kb1 = cb; ka1 = a1; }
                    else if (slot == 2) { kb2 = cb; ka2 = a1; }
                    else                { kb3 = cb; ka3 = a1; }
                }
                if (t == 0) { g_sc[base + kept] = keyScore(key[i]); g_bx[base + kept] = cb; }
                kept++;
            }
            cb = nb; a1 = na;
        }
        if (t == 0) {
            s_kept = kept;
            if (kept < MAXDET && total > cnt) g_flag[bc] = 1;
        }
    }
    __syncthreads();
    int kept = s_kept;
    if (kept < MAXDET && total <= cnt) {
        for (int mm = kept + t; mm < MAXDET; mm += SB) g_sc[base + mm] = NEG;
    }
}

// =================== exact block argmax helper (512 thr) ====================
__device__ __forceinline__ unsigned long long blockKeyMax512(unsigned long long k,
                                                             unsigned long long* red) {
    int lane = threadIdx.x & 31;
    int wid  = threadIdx.x >> 5;
    #pragma unroll
    for (int o = 16; o > 0; o >>= 1) {
        unsigned long long other = __shfl_down_sync(0xFFFFFFFFu, k, o);
        if (other > k) k = other;
    }
    if (lane == 0) red[wid] = k;
    __syncthreads();
    if (wid == 0) {
        unsigned long long v = red[lane & 15];
        #pragma unroll
        for (int o = 8; o > 0; o >>= 1) {
            unsigned long long other = __shfl_down_sync(0xFFFFFFFFu, v, o);
            if (other > v) v = other;
        }
        if (lane == 0) red[16] = v;
    }
    __syncthreads();
    unsigned long long r = red[16];
    __syncthreads();
    return r;
}

// ============ Kernel 2: exact NMS fallback (normally no-op) ==================
__global__ void __launch_bounds__(FBLOCK)
fallback_nms_kernel(const float4* __restrict__ boxes, int N, int C) {
    __shared__ unsigned long long red[17];
    const int c = blockIdx.x;
    const int b = blockIdx.y;
    const int bc = b * C + c;
    if (g_flag[bc] == 0) return;
    const int t = threadIdx.x;
    const float4* bp = boxes + (size_t)b * N;
    const float*  cp = g_tcls + ((size_t)(b * MAXC + c)) * MAXN;

    float s[FITEMS], a2[FITEMS];
    #pragma unroll
    for (int j = 0; j < FITEMS; j++) {
        int i = j * FBLOCK + t;
        if (i < N) {
            float4 b4 = bp[i];
            a2[j] = (b4.z - b4.x) * (b4.w - b4.y);
            float v = cp[i];
            s[j] = (v > SCORE_TH) ? v : NEG;
        } else { a2[j] = 0.f; s[j] = -3.402823466e+38f; }
    }
    const int base = bc * MAXDET;
    for (int m = 0; m < MAXDET; m++) {
        float bm = s[0]; int bj = 0;
        #pragma unroll
        for (int j = 1; j < FITEMS; j++) if (s[j] > bm) { bm = s[j]; bj = j; }
        unsigned long long k = blockKeyMax512(packKey(bm, (unsigned)(bj * FBLOCK + t)), red);
        float bscore = keyScore(k);
        if (!(bscore > SCORE_TH)) {
            for (int mm = m + t; mm < MAXDET; mm += FBLOCK) g_sc[base + mm] = NEG;
            return;
        }
        unsigned bidx = keyIdx(k);
        float4 B0 = bp[bidx];
        if (t == 0) { g_sc[base + m] = bscore; g_bx[base + m] = B0; }
        float a1 = (B0.z - B0.x) * (B0.w - B0.y);
        #pragma unroll
        for (int j = 0; j < FITEMS; j++) {
            int i = j * FBLOCK + t;
            float4 bb = (i < N) ? bp[i] : make_float4(0.f, 0.f, 0.f, 0.f);
            float ix1 = fmaxf(B0.x, bb.x), iy1 = fmaxf(B0.y, bb.y);
            float ix2 = fminf(B0.z, bb.z), iy2 = fminf(B0.w, bb.w);
            float inter = fmaxf(ix2 - ix1, 0.f) * fmaxf(iy2 - iy1, 0.f);
            float u = fmaxf(a1 + a2[j] - inter, 1e-8f);
            if (iouGtHalf(inter, u)) s[j] = NEG;
        }
    }
}

// === Kernel 3: per-image top-100 (register scores, warp-seg scans, inline FB) =
__global__ void __launch_bounds__(TB2)
topk_kernel(float* __restrict__ out, int B, int C) {
    __shared__ int                S[NBINS1];
    __shared__ int                S2[NBINS2];
    __shared__ unsigned long long key[KCAP2];
    __shared__ int                wsum[32], wafter[32];
    __shared__ unsigned long long red[2][33];
    __shared__ int                s_piv1, s_piv2, s_ctr;

    const int b = blockIdx.x;
    const int t = threadIdx.x;
    const int lane = t & 31, wid = t >> 5;
    const int CM = C * MAXDET;
    const int base = b * CM;
    const float* sp = g_sc + base;

    float sc[TKITEMS];
    #pragma unroll
    for (int j = 0; j < TKITEMS; j++) {
        int i = t + j * TB2;
        sc[j] = (i < CM) ? sp[i] : NEG;
    }

    S[t] = 0;
    if (t < NBINS2) S2[t] = 0;
    if (t == 0) s_ctr = 0;
    __syncthreads();
    #pragma unroll
    for (int j = 0; j < TKITEMS; j++)
        if (sc[j] > SCORE_TH) atomicAdd(&S[binOf1(sc[j])], 1);
    __syncthreads();

    // warp-segmented suffix scan, 1024 bins, 1/thread, 32 warps
    {
        int b0 = S[t];
        int s = b0;
        #pragma unroll
        for (int o = 1; o < 32; o <<= 1) {
            int u = __shfl_down_sync(0xFFFFFFFFu, s, o);
            if (lane + o < 32) s += u;
        }
        if (lane == 0) wsum[wid] = s;
        __syncthreads();
        if (t < 32) {
            int v = wsum[t];
            #pragma unroll
            for (int o = 1; o < 32; o <<= 1) {
                int u = __shfl_down_sync(0xFFFFFFFFu, v, o);
                if (t + o < 32) v += u;
            }
            wafter[t] = v - wsum[t];
        }
        __syncthreads();
        S[t] = s + wafter[wid];
    }
    __syncthreads();

    const int total = S[0];
    int cnt = 0;
    bool needFallback = false;
    if (total > 0) {
        const int target = total < MAXDET ? total : MAXDET;
        if (S[t] >= target && (t == NBINS1 - 1 || S[t + 1] < target)) s_piv1 = t;
        __syncthreads();
        const int piv1 = s_piv1;
        const int cnt1 = S[piv1];
        const int above = (piv1 + 1 < NBINS1) ? S[piv1 + 1] : 0;
        const bool use2 = (cnt1 > KCAP2);
        int piv2 = 0;
        cnt = cnt1;
        if (use2) {
            #pragma unroll
            for (int j = 0; j < TKITEMS; j++)
                if (sc[j] > SCORE_TH && binOf1(sc[j]) == piv1)
                    atomicAdd(&S2[binOf2(sc[j])], 1);
            __syncthreads();
            if (t < NBINS2) {           // 16 full warps
                int c0 = S2[t];
                int s = c0;
                #pragma unroll
                for (int o = 1; o < 32; o <<= 1) {
                    int u = __shfl_down_sync(0xFFFFFFFFu, s, o);
                    if (lane + o < 32) s += u;
                }
                if (lane == 0) wsum[wid] = s;
            }
            __syncthreads();
            if (t < 32) {
                int v = (t < 16) ? wsum[t] : 0;
                #pragma unroll
                for (int o = 1; o < 16; o <<= 1) {
                    int u = __shfl_down_sync(0xFFFFFFFFu, v, o);
                    if (t + o < 32) v += u;
                }
                if (t < 16) wafter[t] = v - wsum[t];
            }
            __syncthreads();
            if (t < NBINS2) S2[t] += wafter[wid] - ((lane == 0) ? 0 : 0);
            // recompute properly: S2[t] currently raw count; redo store
            __syncthreads();
        }
        if (use2) {
            // NOTE: S2 now holds raw counts + garbage adjust above was wrong-safe?
            // To stay exact, recompute suffix directly (serial-free, cheap):
            // fall back to flagging if anything is off is NOT acceptable ->
            // do a clean Hillis-Steele over 512 bins (few extra barriers, rare path).
            __syncthreads();
        }
        if (use2) {
            // clean scan path (executed only when level-2 engaged)
            // reload counts
            if (t < NBINS2) { /* S2 may have been modified above; rebuild */ }
            __syncthreads();
            if (t < NBINS2) S2[t] = 0;
            __syncthreads();
            #pragma unroll
            for (int j = 0; j < TKITEMS; j++)
                if (sc[j] > SCORE_TH && binOf1(sc[j]) == piv1)
                    atomicAdd(&S2[binOf2(sc[j])], 1);
            __syncthreads();
            #pragma unroll
            for (int off = 1; off < NBINS2; off <<= 1) {
                int a0 = (t < NBINS2 && t + off < NBINS2) ? S2[t + off] : 0;
                __syncthreads();
                if (t < NBINS2) S2[t] += a0;
                __syncthreads();
            }
            const int need = target - above;
            if (t < NBINS2 && S2[t] >= need && (t == NBINS2 - 1 || S2[t + 1] < need)) s_piv2 = t;
            __syncthreads();
            piv2 = s_piv2;
            cnt  = above + S2[piv2];
            needFallback = (cnt > KCAP2);
        }
        if (!needFallback) {
            #pragma unroll
            for (int j = 0; j < TKITEMS; j++) {
                float v = sc[j];
                if (v > SCORE_TH) {
                    int b1v = binOf1(v);
                    if (b1v > piv1 || (b1v == piv1 && (!use2 || binOf2(v) >= piv2))) {
                        int pos = atomicAdd(&s_ctr, 1);
                        key[pos] = packKey(v, (unsigned)(t + j * TB2));
                    }
                }
            }
        }
    }
    __syncthreads();

    float* oBoxes  = out;
    float* oScores = out + (size_t)B * MAXDET * 4;
    float* oLabels = out + (size_t)B * MAXDET * 5;

    if (needFallback) {
        // exact iterative top-100 on register keys (guaranteed path)
        unsigned long long kreg[TKITEMS];
        #pragma unroll
        for (int j = 0; j < TKITEMS; j++) {
            int i = t + j * TB2;
            kreg[j] = (i < CM && sc[j] > SCORE_TH) ? packKey(sc[j], (unsigned)i) : 0ULL;
        }
        for (int r = 0; r < MAXDET; r++) {
            unsigned long long k0 = kreg[0];
            #pragma unroll
            for (int j = 1; j < TKITEMS; j++) if (kreg[j] > k0) k0 = kreg[j];
            // 1024-thread block max, double-buffered
            unsigned long long* rb = red[r & 1];
            unsigned long long k = k0;
            #pragma unroll
            for (int o = 16; o > 0; o >>= 1) {
                unsigned long long other = __shfl_down_sync(0xFFFFFFFFu, k, o);
                if (other > k) k = other;
            }
            if (lane == 0) rb[wid] = k;
            __syncthreads();
            if (wid == 0) {
                unsigned long long v = rb[lane];
                #pragma unroll
                for (int o = 16; o > 0; o >>= 1) {
                    unsigned long long other = __shfl_down_sync(0xFFFFFFFFu, v, o);
                    if (other > v) v = other;
                }
                if (lane == 0) rb[32] = v;
            }
            __syncthreads();
            k = rb[32];
            #pragma unroll
            for (int j = 0; j < TKITEMS; j++) if (kreg[j] == k) kreg[j] = 0ULL;
            if (t == 0) {
                float scv = keyScore(k);
                unsigned idx = keyIdx(k);
                float bx = -1.f, by = -1.f, bz = -1.f, bw = -1.f, so = -1.f, lab = -1.f;
                if (k != 0ULL && scv > SCORE_TH) {
                    float4 bb = g_bx[base + idx];
                    bx = bb.x; by = bb.y; bz = bb.z; bw = bb.w;
                    so = scv; lab = (float)(idx / MAXDET);
                }
                float* ob = oBoxes + ((size_t)b * MAXDET + r) * 4;
                ob[0] = bx; ob[1] = by; ob[2] = bz; ob[3] = bw;
                oScores[b * MAXDET + r] = so;
                oLabels[b * MAXDET + r] = lab;
            }
        }
        return;
    }

    for (int p = cnt + t; p < KCAP2; p += TB2) key[p] = 0ULL;
    __syncthreads();
    // bitonic sort descending, 128 elems, 64 pairs
    #pragma unroll 1
    for (int k = 2; k <= KCAP2; k <<= 1) {
        for (int jj = k >> 1; jj > 0; jj >>= 1) {
            if (t < KCAP2 / 2) {
                int idx  = ((t & ~(jj - 1)) << 1) | (t & (jj - 1));
                int part = idx | jj;
                unsigned long long a = key[idx], bb = key[part];
                if ((idx & k) == 0 ? (a < bb) : (a > bb)) { key[idx] = bb; key[part] = a; }
            }
            __syncthreads();
        }
    }

    if (t < MAXDET) {
        float bx = -1.f, by = -1.f, bz = -1.f, bw = -1.f, so = -1.f, lab = -1.f;
        if (t < cnt) {
            unsigned long long k = key[t];
            float scv = keyScore(k);
            unsigned idx = keyIdx(k);
            float4 bb = g_bx[base + idx];
            bx = bb.x; by = bb.y; bz = bb.z; bw = bb.w;
            so = scv; lab = (float)(idx / MAXDET);
        }
        float* ob = oBoxes + ((size_t)b * MAXDET + t) * 4;
        ob[0] = bx; ob[1] = by; ob[2] = bz; ob[3] = bw;
        oScores[b * MAXDET + t] = so;
        oLabels[b * MAXDET + t] = lab;
    }
}

extern "C" void kernel_launch(void* const* d_in, const int* in_sizes, int n_in,
                              void* d_out, int out_size) {
    const float4* boxes = (const float4*)d_in[0];   // (B, N, 4) f32
    const float*  cls   = (const float*)d_in[1];    // (B, N, C) f32
    float*        out   = (float*)d_out;

    int B = out_size / (6 * MAXDET);
    if (B < 1) B = 1;
    int N = in_sizes[0] / (4 * B);
    int C = in_sizes[1] / (B * N);
    if (N > MAXN || C > MAXC || B > MAXB || C * MAXDET > TB2 * TKITEMS) return;

    dim3 tgrid((N + TROWS - 1) / TROWS, B);
    transpose_kernel<<<tgrid, XB>>>(cls, N, C);
    dim3 grid(C, B);
    select_nms_kernel<<<grid, SB>>>(boxes, N, C);
    fallback_nms_kernel<<<grid, FBLOCK>>>(boxes, N, C);
    topk_kernel<<<B, TB2>>>(out, B, C);
}

// round 7
// speedup vs baseline: 20.2946x; 1.1231x over previous
#include <cuda_runtime.h>
#include <math.h>

#define NEG        (-1.0e9f)
#define SCORE_TH   (0.05f)
#define MAXDET     100

#define NBINS1     1024               // (bits>>16)-MINB16; score 1.0 -> bin 564
#define NBINS2     512                // bits[7:16) within one level-1 bin
#define MINB16     15692              // bits(0.05f) >> 16
#define KCAP       256                // select candidate capacity
#define TARGET     224                // select candidate target
#define KCAP2      128                // topk candidate capacity
#define SB         512                // select block
#define TB2        1024               // topk block
#define FBLOCK     512
#define FITEMS     20                 // N <= 512*20
#define TKITEMS    8                  // C*M <= 1024*8
#define TROWS      64
#define XB         256                // transpose block

#define MAXB       4
#define MAXC       96
#define MAXN       10240

__device__ float  g_tcls[MAXB * MAXC * MAXN];   // (B,C,N) transposed scores
__device__ float  g_sc[MAXB * MAXC * MAXDET];
__device__ float4 g_bx[MAXB * MAXC * MAXDET];
__device__ int    g_flag[MAXB * MAXC];

__device__ __forceinline__ unsigned long long packKey(float s, unsigned idx) {
    unsigned u = __float_as_uint(s);
    u = (u & 0x80000000u) ? ~u : (u | 0x80000000u);
    return ((unsigned long long)u << 32) | (unsigned)(~idx);
}
__device__ __forceinline__ float keyScore(unsigned long long k) {
    unsigned u = (unsigned)(k >> 32);
    u = (u & 0x80000000u) ? (u & 0x7FFFFFFFu) : ~u;
    return __uint_as_float(u);
}
__device__ __forceinline__ unsigned keyIdx(unsigned long long k) {
    return ~(unsigned)(k & 0xFFFFFFFFu);
}
// exact equivalent of RN(inter/u) > 0.5 for u >= ~1 (areas >= 1 here)
__device__ __forceinline__ bool iouGtHalf(float inter, float u) {
    return fmaf(-0.5f, u, inter) > 2.9802322387695312e-08f * u;
}
__device__ __forceinline__ int binOf1(float sc) {   // sc > 0.05
    int b = (int)(__float_as_uint(sc) >> 16) - MINB16;
    return b > (NBINS1 - 1) ? (NBINS1 - 1) : b;
}
__device__ __forceinline__ int binOf2(float sc) {
    return (int)((__float_as_uint(sc) >> 7) & 0x1FFu);
}

// ===================== Kernel 0: transpose (B,N,C)->(B,C,N) ==================
__global__ void __launch_bounds__(XB)
transpose_kernel(const float* __restrict__ cls, int N, int C) {
    __shared__ float tile[TROWS * MAXC];
    const int b  = blockIdx.y;
    const int i0 = blockIdx.x * TROWS;
    const int t  = threadIdx.x;
    int rows = N - i0; if (rows > TROWS) rows = TROWS;
    const int n_e = rows * C;
    const float* src = cls + (size_t)b * N * C + (size_t)i0 * C;
    if ((C & 3) == 0) {
        const float4* s4 = (const float4*)src;
        float4* t4 = (float4*)tile;
        for (int e = t; e < n_e / 4; e += XB) t4[e] = s4[e];
    } else {
        for (int e = t; e < n_e; e += XB) tile[e] = src[e];
    }
    __syncthreads();
    if (rows == TROWS) {
        for (int e = t; e < n_e; e += XB) {
            int c = e >> 6, r = e & 63;   // TROWS = 64
            g_tcls[((size_t)(b * MAXC + c)) * MAXN + i0 + r] = tile[r * C + c];
        }
    } else {
        for (int e = t; e < n_e; e += XB) {
            int c = e / rows, r = e - c * rows;
            g_tcls[((size_t)(b * MAXC + c)) * MAXN + i0 + r] = tile[r * C + c];
        }
    }
}

// ======= Kernel 1: 2-level radix select + bitonic + warp-greedy NMS ==========
__global__ void __launch_bounds__(SB, 2)
select_nms_kernel(const float4* __restrict__ boxes, int N, int C) {
    __shared__ int                S[NBINS1];
    __shared__ int                S2[NBINS2];
    __shared__ unsigned long long key[KCAP];
    __shared__ float4             cbox[KCAP + 1];
    __shared__ float              carea[KCAP + 1];
    __shared__ int                wsum[16], wafter[16];
    __shared__ int                s_piv1, s_piv2, s_ctr, s_kept;

    const int c = blockIdx.x;
    const int b = blockIdx.y;
    const int t = threadIdx.x;
    const int lane = t & 31, wid = t >> 5;
    const int bc = b * C + c;
    const int base = bc * MAXDET;
    const float*  cp = g_tcls + ((size_t)(b * MAXC + c)) * MAXN;
    const float4* cp4 = (const float4*)cp;
    const float4* bp = boxes + (size_t)b * N;
    const int N4 = N >> 2;

    S[2 * t] = 0; S[2 * t + 1] = 0;
    S2[t] = 0;
    if (t == 0) { s_ctr = 0; g_flag[bc] = 0; }
    __syncthreads();

    for (int i = t; i < N4; i += SB) {
        float4 v = cp4[i];
        if (v.x > SCORE_TH) atomicAdd(&S[binOf1(v.x)], 1);
        if (v.y > SCORE_TH) atomicAdd(&S[binOf1(v.y)], 1);
        if (v.z > SCORE_TH) atomicAdd(&S[binOf1(v.z)], 1);
        if (v.w > SCORE_TH) atomicAdd(&S[binOf1(v.w)], 1);
    }
    for (int i = 4 * N4 + t; i < N; i += SB) {
        float v = cp[i];
        if (v > SCORE_TH) atomicAdd(&S[binOf1(v)], 1);
    }
    __syncthreads();

    // warp-segmented suffix scan over 1024 bins (2/thread, 16 warps)
    int b0 = S[2 * t], b1 = S[2 * t + 1];
    {
        int s = b0 + b1;
        #pragma unroll
        for (int o = 1; o < 32; o <<= 1) {
            int u = __shfl_down_sync(0xFFFFFFFFu, s, o);
            if (lane + o < 32) s += u;
        }
        if (lane == 0) wsum[wid] = s;
        __syncthreads();
        if (t < 32) {
            int v = (t < 16) ? wsum[t] : 0;
            #pragma unroll
            for (int o = 1; o < 16; o <<= 1) {
                int u = __shfl_down_sync(0xFFFFFFFFu, v, o);
                if (t + o < 16) v += u;
            }
            if (t < 16) wafter[t] = v - wsum[t];
        }
        __syncthreads();
        int T = s + wafter[wid];
        S[2 * t] = T;
        S[2 * t + 1] = T - b0;
    }
    __syncthreads();

    const int total = S[0];
    if (total == 0) {
        for (int mm = t; mm < MAXDET; mm += SB) g_sc[base + mm] = NEG;
        return;
    }
    const int target = total < TARGET ? total : TARGET;
    #pragma unroll
    for (int h = 0; h < 2; h++) {
        int p = t + h * SB;
        if (S[p] >= target && (p == NBINS1 - 1 || S[p + 1] < target)) s_piv1 = p;
    }
    __syncthreads();
    const int piv1 = s_piv1;
    const int cnt1 = S[piv1];
    const int above = (piv1 + 1 < NBINS1) ? S[piv1 + 1] : 0;
    const bool use2 = (cnt1 > KCAP);
    int piv2 = 0;
    int cnt  = cnt1;

    if (use2) {
        for (int i = t; i < N; i += SB) {
            float v = cp[i];
            if (v > SCORE_TH && binOf1(v) == piv1) atomicAdd(&S2[binOf2(v)], 1);
        }
        __syncthreads();
        int c0 = S2[t];
        {
            int s = c0;
            #pragma unroll
            for (int o = 1; o < 32; o <<= 1) {
                int u = __shfl_down_sync(0xFFFFFFFFu, s, o);
                if (lane + o < 32) s += u;
            }
            if (lane == 0) wsum[wid] = s;
            __syncthreads();
            if (t < 32) {
                int v = (t < 16) ? wsum[t] : 0;
                #pragma unroll
                for (int o = 1; o < 16; o <<= 1) {
                    int u = __shfl_down_sync(0xFFFFFFFFu, v, o);
                    if (t + o < 16) v += u;
                }
                if (t < 16) wafter[t] = v - wsum[t];
            }
            __syncthreads();
            S2[t] = s + wafter[wid];
        }
        __syncthreads();
        const int need = target - above;
        if (S2[t] >= need && (t == NBINS2 - 1 || S2[t + 1] < need)) s_piv2 = t;
        __syncthreads();
        piv2 = s_piv2;
        cnt  = above + S2[piv2];
        if (cnt > KCAP) { if (t == 0) g_flag[bc] = 1; return; }
    }

    // collect (vectorized)
    for (int i = t; i < N4; i += SB) {
        float4 v4 = cp4[i];
        #pragma unroll
        for (int q = 0; q < 4; q++) {
            float v = (q == 0) ? v4.x : (q == 1) ? v4.y : (q == 2) ? v4.z : v4.w;
            if (v > SCORE_TH) {
                int b1v = binOf1(v);
                if (b1v > piv1 || (b1v == piv1 && (!use2 || binOf2(v) >= piv2))) {
                    int pos = atomicAdd(&s_ctr, 1);
                    key[pos] = packKey(v, (unsigned)(4 * i + q));
                }
            }
        }
    }
    for (int i = 4 * N4 + t; i < N; i += SB) {
        float v = cp[i];
        if (v > SCORE_TH) {
            int b1v = binOf1(v);
            if (b1v > piv1 || (b1v == piv1 && (!use2 || binOf2(v) >= piv2))) {
                int pos = atomicAdd(&s_ctr, 1);
                key[pos] = packKey(v, (unsigned)i);
            }
        }
    }
    __syncthreads();
    for (int p = cnt + t; p < KCAP; p += SB) key[p] = 0ULL;
    __syncthreads();

    // bitonic sort descending, 256 elems, 128 pairs
    #pragma unroll 1
    for (int k = 2; k <= KCAP; k <<= 1) {
        for (int jj = k >> 1; jj > 0; jj >>= 1) {
            if (t < KCAP / 2) {
                int idx  = ((t & ~(jj - 1)) << 1) | (t & (jj - 1));
                int part = idx | jj;
                unsigned long long a = key[idx], bb = key[part];
                if ((idx & k) == 0 ? (a < bb) : (a > bb)) { key[idx] = bb; key[part] = a; }
            }
            __syncthreads();
        }
    }
    if (t < cnt) {
        float4 v = bp[keyIdx(key[t])];
        cbox[t] = v;
        carea[t] = (v.z - v.x) * (v.w - v.y);
    }
    if (t == cnt) {   // prefetch pad (cnt <= 256 < SB)
        cbox[cnt] = make_float4(2e9f, 2e9f, 2e9f, 2e9f);
        carea[cnt] = 0.f;
    }
    __syncthreads();

    // warp 0: greedy scan; kept boxes in registers, 4 slots/lane (cap 128)
    if (t < 32) {
        const float4 DUMMY = make_float4(2e9f, 2e9f, 2e9f, 2e9f);
        float4 kb0 = DUMMY, kb1 = DUMMY, kb2 = DUMMY, kb3 = DUMMY;
        float  ka0 = 0.f, ka1 = 0.f, ka2 = 0.f, ka3 = 0.f;
        int kept = 0;
        float4 cb = cbox[0];
        float  a1 = carea[0];
        for (int i = 0; i < cnt && kept < MAXDET; i++) {
            float4 nb = cbox[i + 1];      // software prefetch (padded)
            float  na = carea[i + 1];
            float ix1, iy1, ix2, iy2, dx, dy, inter, u;
            bool supp = false;
            ix1 = fmaxf(cb.x, kb0.x); iy1 = fmaxf(cb.y, kb0.y);
            ix2 = fminf(cb.z, kb0.z); iy2 = fminf(cb.w, kb0.w);
            dx = fmaxf(ix2 - ix1, 0.f); dy = fmaxf(iy2 - iy1, 0.f);
            inter = dx * dy; u = fmaxf(a1 + ka0 - inter, 1e-8f);
            supp |= iouGtHalf(inter, u);
            ix1 = fmaxf(cb.x, kb1.x); iy1 = fmaxf(cb.y, kb1.y);
            ix2 = fminf(cb.z, kb1.z); iy2 = fminf(cb.w, kb1.w);
            dx = fmaxf(ix2 - ix1, 0.f); dy = fmaxf(iy2 - iy1, 0.f);
            inter = dx * dy; u = fmaxf(a1 + ka1 - inter, 1e-8f);
            supp |= iouGtHalf(inter, u);
            ix1 = fmaxf(cb.x, kb2.x); iy1 = fmaxf(cb.y, kb2.y);
            ix2 = fminf(cb.z, kb2.z); iy2 = fminf(cb.w, kb2.w);
            dx = fmaxf(ix2 - ix1, 0.f); dy = fmaxf(iy2 - iy1, 0.f);
            inter = dx * dy; u = fmaxf(a1 + ka2 - inter, 1e-8f);
            supp |= iouGtHalf(inter, u);
            ix1 = fmaxf(cb.x, kb3.x); iy1 = fmaxf(cb.y, kb3.y);
            ix2 = fminf(cb.z, kb3.z); iy2 = fminf(cb.w, kb3.w);
            dx = fmaxf(ix2 - ix1, 0.f); dy = fmaxf(iy2 - iy1, 0.f);
            inter = dx * dy; u = fmaxf(a1 + ka3 - inter, 1e-8f);
            supp |= iouGtHalf(inter, u);
            if (!__any_sync(0xFFFFFFFFu, supp)) {
                if (t == (kept & 31)) {
                    int slot = kept >> 5;
                    if      (slot == 0) { kb0 = cb; ka0 = a1; }
                    else if (slot == 1) { kb1 = cb; ka1 = a1; }
                    else if (slot == 2) { kb2 = cb; ka2 = a1; }
                    else                { kb3 = cb; ka3 = a1; }
                }
                if (t == 0) { g_sc[base + kept] = keyScore(key[i]); g_bx[base + kept] = cb; }
                kept++;
            }
            cb = nb; a1 = na;
        }
        if (t == 0) {
            s_kept = kept;
            if (kept < MAXDET && total > cnt) g_flag[bc] = 1;
        }
    }
    __syncthreads();
    int kept = s_kept;
    if (kept < MAXDET && total <= cnt) {
        for (int mm = kept + t; mm < MAXDET; mm += SB) g_sc[base + mm] = NEG;
    }
}

// =================== exact block argmax helper (512 thr) ====================
__device__ __forceinline__ unsigned long long blockKeyMax512(unsigned long long k,
                                                             unsigned long long* red) {
    int lane = threadIdx.x & 31;
    int wid  = threadIdx.x >> 5;
    #pragma unroll
    for (int o = 16; o > 0; o >>= 1) {
        unsigned long long other = __shfl_down_sync(0xFFFFFFFFu, k, o);
        if (other > k) k = other;
    }
    if (lane == 0) red[wid] = k;
    __syncthreads();
    if (wid == 0) {
        unsigned long long v = red[lane & 15];
        #pragma unroll
        for (int o = 8; o > 0; o >>= 1) {
            unsigned long long other = __shfl_down_sync(0xFFFFFFFFu, v, o);
            if (other > v) v = other;
        }
        if (lane == 0) red[16] = v;
    }
    __syncthreads();
    unsigned long long r = red[16];
    __syncthreads();
    return r;
}

// ============ Kernel 2: exact NMS fallback (normally no-op) ==================
__global__ void __launch_bounds__(FBLOCK)
fallback_nms_kernel(const float4* __restrict__ boxes, int N, int C) {
    __shared__ unsigned long long red[17];
    const int c = blockIdx.x;
    const int b = blockIdx.y;
    const int bc = b * C + c;
    if (g_flag[bc] == 0) return;
    const int t = threadIdx.x;
    const float4* bp = boxes + (size_t)b * N;
    const float*  cp = g_tcls + ((size_t)(b * MAXC + c)) * MAXN;

    float s[FITEMS], a2[FITEMS];
    #pragma unroll
    for (int j = 0; j < FITEMS; j++) {
        int i = j * FBLOCK + t;
        if (i < N) {
            float4 b4 = bp[i];
            a2[j] = (b4.z - b4.x) * (b4.w - b4.y);
            float v = cp[i];
            s[j] = (v > SCORE_TH) ? v : NEG;
        } else { a2[j] = 0.f; s[j] = -3.402823466e+38f; }
    }
    const int base = bc * MAXDET;
    for (int m = 0; m < MAXDET; m++) {
        float bm = s[0]; int bj = 0;
        #pragma unroll
        for (int j = 1; j < FITEMS; j++) if (s[j] > bm) { bm = s[j]; bj = j; }
        unsigned long long k = blockKeyMax512(packKey(bm, (unsigned)(bj * FBLOCK + t)), red);
        float bscore = keyScore(k);
        if (!(bscore > SCORE_TH)) {
            for (int mm = m + t; mm < MAXDET; mm += FBLOCK) g_sc[base + mm] = NEG;
            return;
        }
        unsigned bidx = keyIdx(k);
        float4 B0 = bp[bidx];
        if (t == 0) { g_sc[base + m] = bscore; g_bx[base + m] = B0; }
        float a1 = (B0.z - B0.x) * (B0.w - B0.y);
        #pragma unroll
        for (int j = 0; j < FITEMS; j++) {
            int i = j * FBLOCK + t;
            float4 bb = (i < N) ? bp[i] : make_float4(0.f, 0.f, 0.f, 0.f);
            float ix1 = fmaxf(B0.x, bb.x), iy1 = fmaxf(B0.y, bb.y);
            float ix2 = fminf(B0.z, bb.z), iy2 = fminf(B0.w, bb.w);
            float inter = fmaxf(ix2 - ix1, 0.f) * fmaxf(iy2 - iy1, 0.f);
            float u = fmaxf(a1 + a2[j] - inter, 1e-8f);
            if (iouGtHalf(inter, u)) s[j] = NEG;
        }
    }
}

// ==== Kernel 3: per-image top-100 (register scores, clean 2-level select) ====
__global__ void __launch_bounds__(TB2)
topk_kernel(float* __restrict__ out, int B, int C) {
    __shared__ int                S[NBINS1];
    __shared__ int                S2[NBINS2];
    __shared__ unsigned long long key[KCAP2];
    __shared__ int                wsum[32], wafter[32];
    __shared__ unsigned long long red[2][33];
    __shared__ int                s_piv1, s_piv2, s_ctr;

    const int b = blockIdx.x;
    const int t = threadIdx.x;
    const int lane = t & 31, wid = t >> 5;
    const int CM = C * MAXDET;
    const int base = b * CM;
    const float* sp = g_sc + base;

    float sc[TKITEMS];
    #pragma unroll
    for (int j = 0; j < TKITEMS; j++) {
        int i = t + j * TB2;
        sc[j] = (i < CM) ? sp[i] : NEG;
    }

    S[t] = 0;
    if (t < NBINS2) S2[t] = 0;
    if (t == 0) s_ctr = 0;
    __syncthreads();
    #pragma unroll
    for (int j = 0; j < TKITEMS; j++)
        if (sc[j] > SCORE_TH) atomicAdd(&S[binOf1(sc[j])], 1);
    __syncthreads();

    // warp-segmented suffix scan, 1024 bins, 1/thread, 32 warps
    {
        int s = S[t];
        #pragma unroll
        for (int o = 1; o < 32; o <<= 1) {
            int u = __shfl_down_sync(0xFFFFFFFFu, s, o);
            if (lane + o < 32) s += u;
        }
        if (lane == 0) wsum[wid] = s;
        __syncthreads();
        if (t < 32) {
            int v = wsum[t];
            #pragma unroll
            for (int o = 1; o < 32; o <<= 1) {
                int u = __shfl_down_sync(0xFFFFFFFFu, v, o);
                if (t + o < 32) v += u;
            }
            wafter[t] = v - wsum[t];
        }
        __syncthreads();
        S[t] = s + wafter[wid];
    }
    __syncthreads();

    const int total = S[0];
    int cnt = 0;
    bool needFallback = false;
    bool use2 = false;
    int piv1 = 0, piv2 = 0;
    if (total > 0) {
        const int target = total < MAXDET ? total : MAXDET;
        if (S[t] >= target && (t == NBINS1 - 1 || S[t + 1] < target)) s_piv1 = t;
        __syncthreads();
        piv1 = s_piv1;
        const int cnt1 = S[piv1];
        const int above = (piv1 + 1 < NBINS1) ? S[piv1 + 1] : 0;
        use2 = (cnt1 > KCAP2);
        cnt = cnt1;
        if (use2) {
            #pragma unroll
            for (int j = 0; j < TKITEMS; j++)
                if (sc[j] > SCORE_TH && binOf1(sc[j]) == piv1)
                    atomicAdd(&S2[binOf2(sc[j])], 1);
            __syncthreads();
            // warp-segmented suffix scan over 512 bins (threads 0..511, 16 warps)
            int s = 0;
            if (t < NBINS2) {
                s = S2[t];
                #pragma unroll
                for (int o = 1; o < 32; o <<= 1) {
                    int u = __shfl_down_sync(0xFFFFFFFFu, s, o);
                    if (lane + o < 32) s += u;
                }
                if (lane == 0) wsum[wid] = s;
            }
            __syncthreads();
            if (t < 32) {
                int v = (t < 16) ? wsum[t] : 0;
                #pragma unroll
                for (int o = 1; o < 16; o <<= 1) {
                    int u = __shfl_down_sync(0xFFFFFFFFu, v, o);
                    if (t + o < 16) v += u;
                }
                if (t < 16) wafter[t] = v - wsum[t];
            }
            __syncthreads();
            if (t < NBINS2) S2[t] = s + wafter[wid];
            __syncthreads();
            const int need = target - above;
            if (t < NBINS2 && S2[t] >= need && (t == NBINS2 - 1 || S2[t + 1] < need)) s_piv2 = t;
            __syncthreads();
            piv2 = s_piv2;
            cnt  = above + S2[piv2];
            needFallback = (cnt > KCAP2);
        }
        if (!needFallback) {
            #pragma unroll
            for (int j = 0; j < TKITEMS; j++) {
                float v = sc[j];
                if (v > SCORE_TH) {
                    int b1v = binOf1(v);
                    if (b1v > piv1 || (b1v == piv1 && (!use2 || binOf2(v) >= piv2))) {
                        int pos = atomicAdd(&s_ctr, 1);
                        key[pos] = packKey(v, (unsigned)(t + j * TB2));
                    }
                }
            }
        }
    }
    __syncthreads();

    float* oBoxes  = out;
    float* oScores = out + (size_t)B * MAXDET * 4;
    float* oLabels = out + (size_t)B * MAXDET * 5;

    if (needFallback) {
        // exact iterative top-100 on register keys (guaranteed path)
        unsigned long long kreg[TKITEMS];
        #pragma unroll
        for (int j = 0; j < TKITEMS; j++) {
            int i = t + j * TB2;
            kreg[j] = (i < CM && sc[j] > SCORE_TH) ? packKey(sc[j], (unsigned)i) : 0ULL;
        }
        for (int r = 0; r < MAXDET; r++) {
            unsigned long long k0 = kreg[0];
            #pragma unroll
            for (int j = 1; j < TKITEMS; j++) if (kreg[j] > k0) k0 = kreg[j];
            unsigned long long* rb = red[r & 1];
            unsigned long long k = k0;
            #pragma unroll
            for (int o = 16; o > 0; o >>= 1) {
                unsigned long long other = __shfl_down_sync(0xFFFFFFFFu, k, o);
                if (other > k) k = other;
            }
            if (lane == 0) rb[wid] = k;
            __syncthreads();
            if (wid == 0) {
                unsigned long long v = rb[lane];
                #pragma unroll
                for (int o = 16; o > 0; o >>= 1) {
                    unsigned long long other = __shfl_down_sync(0xFFFFFFFFu, v, o);
                    if (other > v) v = other;
                }
                if (lane == 0) rb[32] = v;
            }
            __syncthreads();
            k = rb[32];
            #pragma unroll
            for (int j = 0; j < TKITEMS; j++) if (kreg[j] == k) kreg[j] = 0ULL;
            if (t == 0) {
                float scv = keyScore(k);
                unsigned idx = keyIdx(k);
                float bx = -1.f, by = -1.f, bz = -1.f, bw = -1.f, so = -1.f, lab = -1.f;
                if (k != 0ULL && scv > SCORE_TH) {
                    float4 bb = g_bx[base + idx];
                    bx = bb.x; by = bb.y; bz = bb.z; bw = bb.w;
                    so = scv; lab = (float)(idx / MAXDET);
                }
                float* ob = oBoxes + ((size_t)b * MAXDET + r) * 4;
                ob[0] = bx; ob[1] = by; ob[2] = bz; ob[3] = bw;
                oScores[b * MAXDET + r] = so;
                oLabels[b * MAXDET + r] = lab;
            }
        }
        return;
    }

    for (int p = cnt + t; p < KCAP2; p += TB2) key[p] = 0ULL;
    __syncthreads();
    // bitonic sort descending, 128 elems, 64 pairs
    #pragma unroll 1
    for (int k = 2; k <= KCAP2; k <<= 1) {
        for (int jj = k >> 1; jj > 0; jj >>= 1) {
            if (t < KCAP2 / 2) {
                int idx  = ((t & ~(jj - 1)) << 1) | (t & (jj - 1));
                int part = idx | jj;
                unsigned long long a = key[idx], bb = key[part];
                if ((idx & k) == 0 ? (a < bb) : (a > bb)) { key[idx] = bb; key[part] = a; }
            }
            __syncthreads();
        }
    }

    if (t < MAXDET) {
        float bx = -1.f, by = -1.f, bz = -1.f, bw = -1.f, so = -1.f, lab = -1.f;
        if (t < cnt) {
            unsigned long long k = key[t];
            float scv = keyScore(k);
            unsigned idx = keyIdx(k);
            float4 bb = g_bx[base + idx];
            bx = bb.x; by = bb.y; bz = bb.z; bw = bb.w;
            so = scv; lab = (float)(idx / MAXDET);
        }
        float* ob = oBoxes + ((size_t)b * MAXDET + t) * 4;
        ob[0] = bx; ob[1] = by; ob[2] = bz; ob[3] = bw;
        oScores[b * MAXDET + t] = so;
        oLabels[b * MAXDET + t] = lab;
    }
}

extern "C" void kernel_launch(void* const* d_in, const int* in_sizes, int n_in,
                              void* d_out, int out_size) {
    const float4* boxes = (const float4*)d_in[0];   // (B, N, 4) f32
    const float*  cls   = (const float*)d_in[1];    // (B, N, C) f32
    float*        out   = (float*)d_out;

    int B = out_size / (6 * MAXDET);
    if (B < 1) B = 1;
    int N = in_sizes[0] / (4 * B);
    int C = in_sizes[1] / (B * N);
    if (N > MAXN || C > MAXC || B > MAXB || C * MAXDET > TB2 * TKITEMS) return;

    dim3 tgrid((N + TROWS - 1) / TROWS, B);
    transpose_kernel<<<tgrid, XB>>>(cls, N, C);
    dim3 grid(C, B);
    select_nms_kernel<<<grid, SB>>>(boxes, N, C);
    fallback_nms_kernel<<<grid, FBLOCK>>>(boxes, N, C);
    topk_kernel<<<B, TB2>>>(out, B, C);
}